// round 2
// baseline (speedup 1.0000x reference)
#include <cuda_runtime.h>
#include <cuda_bf16.h>
#include <math.h>

#define H 128
#define H4 32            // H/4 (float4 per row)
#define NMAX 50176
#define WMAT 16384       // 128*128 floats per weight matrix

// ---------------- device scratch (static, no allocation) ----------------
__device__ float g_h [NMAX * H];
__device__ float g_Pu[NMAX * H];
__device__ float g_Pv[NMAX * H];
__device__ float g_a1[NMAX * H];
__device__ float g_a2[NMAX * H];
__device__ float g_g [NMAX * H];

// ---------------- helpers ----------------
__device__ __forceinline__ float silu(float x) {
    return x / (1.0f + expf(-x));
}

__device__ __forceinline__ float4 silu4(float4 a) {
    a.x = silu(a.x); a.y = silu(a.y); a.z = silu(a.z); a.w = silu(a.w);
    return a;
}

// acc[j] += sum_k x[k] * W[k][j], W row-major 128x128 in shared memory.
// x is warp-distributed: lane L holds x[4L..4L+3].
// Each lane accumulates output columns j = 4*lane .. 4*lane+3.
__device__ __forceinline__ void gemv128(const float* __restrict__ sW,
                                        float4 x, float4& acc, int lane)
{
    const float4* W4 = reinterpret_cast<const float4*>(sW);
#pragma unroll 8
    for (int k4 = 0; k4 < 32; ++k4) {
        float v0 = __shfl_sync(0xffffffffu, x.x, k4);
        float v1 = __shfl_sync(0xffffffffu, x.y, k4);
        float v2 = __shfl_sync(0xffffffffu, x.z, k4);
        float v3 = __shfl_sync(0xffffffffu, x.w, k4);
        float4 w0 = W4[(k4 * 4 + 0) * H4 + lane];
        float4 w1 = W4[(k4 * 4 + 1) * H4 + lane];
        float4 w2 = W4[(k4 * 4 + 2) * H4 + lane];
        float4 w3 = W4[(k4 * 4 + 3) * H4 + lane];
        acc.x += v0 * w0.x; acc.y += v0 * w0.y; acc.z += v0 * w0.z; acc.w += v0 * w0.w;
        acc.x += v1 * w1.x; acc.y += v1 * w1.y; acc.z += v1 * w1.z; acc.w += v1 * w1.w;
        acc.x += v2 * w2.x; acc.y += v2 * w2.y; acc.z += v2 * w2.z; acc.w += v2 * w2.w;
        acc.x += v3 * w3.x; acc.y += v3 * w3.y; acc.z += v3 * w3.z; acc.w += v3 * w3.w;
    }
}

// ---------------- kernels ----------------

// h[i] = emb[atom_num[i]]  (float4 granularity)
__global__ void k_gather(const int* __restrict__ atom,
                         const float* __restrict__ emb,
                         float* __restrict__ h, int n)
{
    int i = blockIdx.x * blockDim.x + threadIdx.x;
    if (i >= n * H4) return;
    int row = i >> 5, col = i & 31;
    reinterpret_cast<float4*>(h)[i] =
        reinterpret_cast<const float4*>(emb)[atom[row] * H4 + col];
}

// zero two accumulator tensors
__global__ void k_zero2(float* __restrict__ a, float* __restrict__ b, int n4)
{
    int i = blockIdx.x * blockDim.x + threadIdx.x;
    if (i >= n4) return;
    float4 z = make_float4(0.f, 0.f, 0.f, 0.f);
    reinterpret_cast<float4*>(a)[i] = z;
    reinterpret_cast<float4*>(b)[i] = z;
}

// Y = [silu]( sum_a X_a @ W_a  [+ bias] ) [+ Y_old]
template<int NA, bool SILU_, bool BIAS, bool RESID>
__global__ void __launch_bounds__(512)
k_rowgemm(const float* __restrict__ X0, const float* __restrict__ X1,
          const float* __restrict__ X2,
          const float* __restrict__ W0, const float* __restrict__ W1,
          const float* __restrict__ W2w,
          const float* __restrict__ bias, float* __restrict__ Y, int n)
{
    extern __shared__ float smem[];
    {
        const float* Ws[3] = {W0, W1, W2w};
#pragma unroll
        for (int a = 0; a < NA; ++a) {
            const float4* src = reinterpret_cast<const float4*>(Ws[a]);
            float4* dst = reinterpret_cast<float4*>(smem + a * WMAT);
            for (int i = threadIdx.x; i < WMAT / 4; i += blockDim.x)
                dst[i] = src[i];
        }
    }
    __syncthreads();

    int lane = threadIdx.x & 31;
    int warp = threadIdx.x >> 5;
    int wpb  = blockDim.x >> 5;

    float4 bb = make_float4(0.f, 0.f, 0.f, 0.f);
    if (BIAS) bb = reinterpret_cast<const float4*>(bias)[lane];

    const float* Xs[3] = {X0, X1, X2};

    for (int r = blockIdx.x * wpb + warp; r < n; r += gridDim.x * wpb) {
        float4 acc = bb;
#pragma unroll
        for (int a = 0; a < NA; ++a) {
            float4 x = reinterpret_cast<const float4*>(Xs[a])[r * H4 + lane];
            gemv128(smem + a * WMAT, x, acc, lane);
        }
        if (SILU_) acc = silu4(acc);
        if (RESID) {
            float4 old = reinterpret_cast<const float4*>(Y)[r * H4 + lane];
            acc.x += old.x; acc.y += old.y; acc.z += old.z; acc.w += old.w;
        }
        reinterpret_cast<float4*>(Y)[r * H4 + lane] = acc;
    }
}

// Fused edge block: pre = Pu[u] + Pv[v] + dis*Wdis + b1
//                   t1 = silu(pre); t2 = silu(t1@W2 + b2); m = t2@W3 + b3
//                   atomicAdd m into aOut[u], aOut[v]   (segment_sum over both endpoints)
__global__ void __launch_bounds__(512)
k_edge(const float* __restrict__ Pu, const float* __restrict__ Pv,
       const float* __restrict__ dis,
       const int* __restrict__ idu, const int* __restrict__ idv,
       const float* __restrict__ Wdis, const float* __restrict__ b1,
       const float* __restrict__ W2, const float* __restrict__ b2,
       const float* __restrict__ W3, const float* __restrict__ b3,
       float* __restrict__ aOut, int E)
{
    extern __shared__ float smem[];
    float* sW2   = smem;
    float* sW3   = smem + WMAT;
    float* sWdis = smem + 2 * WMAT;
    float* sB1   = sWdis + H;
    float* sB2   = sWdis + 2 * H;
    float* sB3   = sWdis + 3 * H;

    {
        const float4* s2 = reinterpret_cast<const float4*>(W2);
        const float4* s3 = reinterpret_cast<const float4*>(W3);
        float4* d2 = reinterpret_cast<float4*>(sW2);
        float4* d3 = reinterpret_cast<float4*>(sW3);
        for (int i = threadIdx.x; i < WMAT / 4; i += blockDim.x) {
            d2[i] = s2[i];
            d3[i] = s3[i];
        }
        if (threadIdx.x < H) {
            sWdis[threadIdx.x] = Wdis[threadIdx.x];
            sB1[threadIdx.x]   = b1[threadIdx.x];
            sB2[threadIdx.x]   = b2[threadIdx.x];
            sB3[threadIdx.x]   = b3[threadIdx.x];
        }
    }
    __syncthreads();

    int lane = threadIdx.x & 31;
    int warp = threadIdx.x >> 5;
    int gw   = blockIdx.x * (blockDim.x >> 5) + warp;
    int nw   = gridDim.x * (blockDim.x >> 5);

    float4 wd  = reinterpret_cast<const float4*>(sWdis)[lane];
    float4 bb1 = reinterpret_cast<const float4*>(sB1)[lane];
    float4 bb2 = reinterpret_cast<const float4*>(sB2)[lane];
    float4 bb3 = reinterpret_cast<const float4*>(sB3)[lane];

    for (int e = gw; e < E; e += nw) {
        int u = idu[e];
        int v = idv[e];
        float d = dis[e];

        float4 pu = reinterpret_cast<const float4*>(Pu)[u * H4 + lane];
        float4 pv = reinterpret_cast<const float4*>(Pv)[v * H4 + lane];

        float4 t1;
        t1.x = silu(pu.x + pv.x + d * wd.x + bb1.x);
        t1.y = silu(pu.y + pv.y + d * wd.y + bb1.y);
        t1.z = silu(pu.z + pv.z + d * wd.z + bb1.z);
        t1.w = silu(pu.w + pv.w + d * wd.w + bb1.w);

        float4 t2 = bb2;
        gemv128(sW2, t1, t2, lane);
        t2 = silu4(t2);

        float4 m = bb3;
        gemv128(sW3, t2, m, lane);

        float* pu_out = aOut + (size_t)u * H + lane * 4;
        atomicAdd(pu_out + 0, m.x);
        atomicAdd(pu_out + 1, m.y);
        atomicAdd(pu_out + 2, m.z);
        atomicAdd(pu_out + 3, m.w);
        float* pv_out = aOut + (size_t)v * H + lane * 4;
        atomicAdd(pv_out + 0, m.x);
        atomicAdd(pv_out + 1, m.y);
        atomicAdd(pv_out + 2, m.z);
        atomicAdd(pv_out + 3, m.w);
    }
}

// out[r] = h[r] @ outW + outb     (warp per row, shfl reduce)
__global__ void k_out(const float* __restrict__ h,
                      const float* __restrict__ outW,
                      const float* __restrict__ outb,
                      float* __restrict__ out, int n)
{
    int warp = (blockIdx.x * blockDim.x + threadIdx.x) >> 5;
    int lane = threadIdx.x & 31;
    if (warp >= n) return;

    float4 x = reinterpret_cast<const float4*>(h)[warp * H4 + lane];
    int k0 = lane * 4;
    float s0 = x.x * outW[(k0 + 0) * 3 + 0] + x.y * outW[(k0 + 1) * 3 + 0]
             + x.z * outW[(k0 + 2) * 3 + 0] + x.w * outW[(k0 + 3) * 3 + 0];
    float s1 = x.x * outW[(k0 + 0) * 3 + 1] + x.y * outW[(k0 + 1) * 3 + 1]
             + x.z * outW[(k0 + 2) * 3 + 1] + x.w * outW[(k0 + 3) * 3 + 1];
    float s2 = x.x * outW[(k0 + 0) * 3 + 2] + x.y * outW[(k0 + 1) * 3 + 2]
             + x.z * outW[(k0 + 2) * 3 + 2] + x.w * outW[(k0 + 3) * 3 + 2];
#pragma unroll
    for (int off = 16; off; off >>= 1) {
        s0 += __shfl_xor_sync(0xffffffffu, s0, off);
        s1 += __shfl_xor_sync(0xffffffffu, s1, off);
        s2 += __shfl_xor_sync(0xffffffffu, s2, off);
    }
    if (lane == 0) {
        out[warp * 3 + 0] = s0 + outb[0];
        out[warp * 3 + 1] = s1 + outb[1];
        out[warp * 3 + 2] = s2 + outb[2];
    }
}

// ---------------- host launch ----------------
extern "C" void kernel_launch(void* const* d_in, const int* in_sizes, int n_in,
                              void* d_out, int out_size)
{
    const int*   atom = (const int*)  d_in[0];
    const float* dis1 = (const float*)d_in[1];
    const float* dis2 = (const float*)d_in[2];
    const int*   id1u = (const int*)  d_in[3];
    const int*   id1v = (const int*)  d_in[4];
    const int*   id2u = (const int*)  d_in[5];
    const int*   id2v = (const int*)  d_in[6];
    const float* emb  = (const float*)d_in[7];
    const float* Wu   = (const float*)d_in[8];
    const float* Wv   = (const float*)d_in[9];
    const float* Wdis = (const float*)d_in[10];
    const float* eb1  = (const float*)d_in[11];
    const float* eW2  = (const float*)d_in[12];
    const float* eb2  = (const float*)d_in[13];
    const float* eW3  = (const float*)d_in[14];
    const float* eb3  = (const float*)d_in[15];
    const float* Wh   = (const float*)d_in[16];
    const float* Wa1  = (const float*)d_in[17];
    const float* Wa2  = (const float*)d_in[18];
    const float* ub1  = (const float*)d_in[19];
    const float* uW2  = (const float*)d_in[20];
    const float* ub2  = (const float*)d_in[21];
    const float* outW = (const float*)d_in[22];
    const float* outb = (const float*)d_in[23];

    int n = in_sizes[0];
    int E = in_sizes[3];
    if (n > NMAX) return;

    float *h, *Pu, *Pv, *a1, *a2, *g;
    cudaGetSymbolAddress((void**)&h,  g_h);
    cudaGetSymbolAddress((void**)&Pu, g_Pu);
    cudaGetSymbolAddress((void**)&Pv, g_Pv);
    cudaGetSymbolAddress((void**)&a1, g_a1);
    cudaGetSymbolAddress((void**)&a2, g_a2);
    cudaGetSymbolAddress((void**)&g,  g_g);

    const int SM_GEMM1 = WMAT * 4;                 // 64 KB
    const int SM_GEMM3 = 3 * WMAT * 4;             // 192 KB
    const int SM_EDGE  = (2 * WMAT + 4 * H) * 4;   // 130 KB + biases

    cudaFuncSetAttribute(k_rowgemm<1, false, false, false>,
                         cudaFuncAttributeMaxDynamicSharedMemorySize, SM_GEMM1);
    cudaFuncSetAttribute(k_rowgemm<3, true, true, false>,
                         cudaFuncAttributeMaxDynamicSharedMemorySize, SM_GEMM3);
    cudaFuncSetAttribute(k_rowgemm<1, false, true, true>,
                         cudaFuncAttributeMaxDynamicSharedMemorySize, SM_GEMM1);
    cudaFuncSetAttribute(k_edge,
                         cudaFuncAttributeMaxDynamicSharedMemorySize, SM_EDGE);

    int gthreads = n * H4;
    int gblocks  = (gthreads + 255) / 256;

    k_gather<<<gblocks, 256>>>(atom, emb, h, n);

    for (int L = 0; L < 2; ++L) {
        k_zero2<<<gblocks, 256>>>(a1, a2, n * H4);

        int i1 = 2 * L, i2 = 2 * L + 1;

        // edge block i1 (graph 1) -> a1
        k_rowgemm<1, false, false, false><<<444, 512, SM_GEMM1>>>(
            h, 0, 0, Wu + i1 * WMAT, 0, 0, 0, Pu, n);
        k_rowgemm<1, false, false, false><<<444, 512, SM_GEMM1>>>(
            h, 0, 0, Wv + i1 * WMAT, 0, 0, 0, Pv, n);
        k_edge<<<148, 512, SM_EDGE>>>(
            Pu, Pv, dis1, id1u, id1v,
            Wdis + i1 * H, eb1 + i1 * H,
            eW2 + i1 * WMAT, eb2 + i1 * H,
            eW3 + i1 * WMAT, eb3 + i1 * H, a1, E);

        // edge block i2 (graph 2) -> a2
        k_rowgemm<1, false, false, false><<<444, 512, SM_GEMM1>>>(
            h, 0, 0, Wu + i2 * WMAT, 0, 0, 0, Pu, n);
        k_rowgemm<1, false, false, false><<<444, 512, SM_GEMM1>>>(
            h, 0, 0, Wv + i2 * WMAT, 0, 0, 0, Pv, n);
        k_edge<<<148, 512, SM_EDGE>>>(
            Pu, Pv, dis2, id2u, id2v,
            Wdis + i2 * H, eb1 + i2 * H,
            eW2 + i2 * WMAT, eb2 + i2 * H,
            eW3 + i2 * WMAT, eb3 + i2 * H, a2, E);

        // atom update L
        k_rowgemm<3, true, true, false><<<148, 512, SM_GEMM3>>>(
            h, a1, a2,
            Wh + L * WMAT, Wa1 + L * WMAT, Wa2 + L * WMAT,
            ub1 + L * H, g, n);
        k_rowgemm<1, false, true, true><<<444, 512, SM_GEMM1>>>(
            g, 0, 0, uW2 + L * WMAT, 0, 0, ub2 + L * H, h, n);
    }

    k_out<<<gblocks, 256>>>(h, outW, outb, (float*)d_out, n);
}

// round 5
// speedup vs baseline: 3.3921x; 3.3921x over previous
#include <cuda_runtime.h>
#include <cuda_bf16.h>
#include <math.h>

#define H 128
#define H4 32
#define NMAX 50176
#define WMAT 16384   // packed weight footprint in unsigneds per matrix (hi+lo)

// ---------------- device scratch (static, no allocation) ----------------
__device__ float g_h [NMAX * H];
__device__ float g_Pu[NMAX * H];
__device__ float g_Pv[NMAX * H];
__device__ float g_a1[NMAX * H];
__device__ float g_a2[NMAX * H];
__device__ float g_g [NMAX * H];
__device__ unsigned g_pack[24 * WMAT];   // bf16 hi/lo fragment-packed weights

// ---------------- helpers ----------------
__device__ __forceinline__ float silu(float x) { return x / (1.0f + __expf(-x)); }

// pack two floats to bf16x2: low half = a, high half = b
__device__ __forceinline__ unsigned pbf2(float a, float b) {
    unsigned r;
    asm("cvt.rn.bf16x2.f32 %0, %1, %2;" : "=r"(r) : "f"(b), "f"(a));
    return r;
}

// split x into bf16 hi + fp32 residual
__device__ __forceinline__ void bsplit(float x, float& hi, float& lo) {
    __nv_bfloat16 h = __float2bfloat16(x);
    hi = __bfloat162float(h);
    lo = x - hi;
}

// m16n8k16 bf16 mma, D += A*B
__device__ __forceinline__ void mma16(float* c, const unsigned* a, uint2 b) {
    asm volatile(
        "mma.sync.aligned.m16n8k16.row.col.f32.bf16.bf16.f32 "
        "{%0,%1,%2,%3},{%4,%5,%6,%7},{%8,%9},{%0,%1,%2,%3};"
        : "+f"(c[0]), "+f"(c[1]), "+f"(c[2]), "+f"(c[3])
        : "r"(a[0]), "r"(a[1]), "r"(a[2]), "r"(a[3]), "r"(b.x), "r"(b.y));
}

// vectorized reduction atomic: aOut[0..3] += v
__device__ __forceinline__ void redv4(float* p, float4 v) {
    asm volatile("red.global.add.v4.f32 [%0], {%1,%2,%3,%4};"
                 :: "l"(p), "f"(v.x), "f"(v.y), "f"(v.z), "f"(v.w) : "memory");
}

// ---------------- weight packing ----------------
// For each matrix (128x128 row-major fp32), build m16n8k16 B-fragments
// (B col-major K x N) for hi and lo bf16 splits:
//   per (nb 0..15, kb 0..7, lane): uint2 { {B[k0][n],B[k0+1][n]}, {B[k0+8][n],B[k0+9][n]} }
//   k0 = kb*16 + 2*(lane&3), n = nb*8 + (lane>>2)
// layout (uint2 units): hi at  m*WMAT/2 + (nb*8+kb)*32 + lane ; lo at +4096.
__global__ void k_pack(const float* __restrict__ Wu,  const float* __restrict__ Wv,
                       const float* __restrict__ eW2, const float* __restrict__ eW3,
                       const float* __restrict__ Wh,  const float* __restrict__ Wa1,
                       const float* __restrict__ Wa2, const float* __restrict__ uW2)
{
    int m = blockIdx.y;
    const float* src;
    if      (m < 4)  src = Wu  + m * H * H;
    else if (m < 8)  src = Wv  + (m - 4) * H * H;
    else if (m < 12) src = eW2 + (m - 8) * H * H;
    else if (m < 16) src = eW3 + (m - 12) * H * H;
    else if (m < 18) src = Wh  + (m - 16) * H * H;
    else if (m < 20) src = Wa1 + (m - 18) * H * H;
    else if (m < 22) src = Wa2 + (m - 20) * H * H;
    else             src = uW2 + (m - 22) * H * H;

    uint2* dhi = reinterpret_cast<uint2*>(g_pack + m * WMAT);
    uint2* dlo = dhi + 4096;

    for (int idx = blockIdx.x * blockDim.x + threadIdx.x; idx < 4096;
         idx += gridDim.x * blockDim.x) {
        int lane = idx & 31, kbnb = idx >> 5;
        int t = lane & 3, g = lane >> 2;
        int kb = kbnb & 7, nb = kbnb >> 3;
        int k0 = kb * 16 + 2 * t;
        int n  = nb * 8 + g;
        float w0 = src[(k0    ) * H + n];
        float w1 = src[(k0 + 1) * H + n];
        float w8 = src[(k0 + 8) * H + n];
        float w9 = src[(k0 + 9) * H + n];
        float h0, l0, h1, l1, h8, l8, h9, l9;
        bsplit(w0, h0, l0); bsplit(w1, h1, l1);
        bsplit(w8, h8, l8); bsplit(w9, h9, l9);
        dhi[idx] = make_uint2(pbf2(h0, h1), pbf2(h8, h9));
        dlo[idx] = make_uint2(pbf2(l0, l1), pbf2(l8, l9));
    }
}

// ---------------- misc kernels ----------------
__global__ void k_gather(const int* __restrict__ atom,
                         const float* __restrict__ emb,
                         float* __restrict__ h, int n)
{
    int i = blockIdx.x * blockDim.x + threadIdx.x;
    if (i >= n * H4) return;
    int row = i >> 5, col = i & 31;
    reinterpret_cast<float4*>(h)[i] =
        reinterpret_cast<const float4*>(emb)[atom[row] * H4 + col];
}

__global__ void k_zero2(float* __restrict__ a, float* __restrict__ b, int n4)
{
    int i = blockIdx.x * blockDim.x + threadIdx.x;
    if (i >= n4) return;
    float4 z = make_float4(0.f, 0.f, 0.f, 0.f);
    reinterpret_cast<float4*>(a)[i] = z;
    reinterpret_cast<float4*>(b)[i] = z;
}

__global__ void k_out(const float* __restrict__ h,
                      const float* __restrict__ outW,
                      const float* __restrict__ outb,
                      float* __restrict__ out, int n)
{
    int warp = (blockIdx.x * blockDim.x + threadIdx.x) >> 5;
    int lane = threadIdx.x & 31;
    if (warp >= n) return;
    float4 x = reinterpret_cast<const float4*>(h)[warp * H4 + lane];
    int k0 = lane * 4;
    float s0 = x.x * outW[(k0+0)*3+0] + x.y * outW[(k0+1)*3+0]
             + x.z * outW[(k0+2)*3+0] + x.w * outW[(k0+3)*3+0];
    float s1 = x.x * outW[(k0+0)*3+1] + x.y * outW[(k0+1)*3+1]
             + x.z * outW[(k0+2)*3+1] + x.w * outW[(k0+3)*3+1];
    float s2 = x.x * outW[(k0+0)*3+2] + x.y * outW[(k0+1)*3+2]
             + x.z * outW[(k0+2)*3+2] + x.w * outW[(k0+3)*3+2];
#pragma unroll
    for (int off = 16; off; off >>= 1) {
        s0 += __shfl_xor_sync(0xffffffffu, s0, off);
        s1 += __shfl_xor_sync(0xffffffffu, s1, off);
        s2 += __shfl_xor_sync(0xffffffffu, s2, off);
    }
    if (lane == 0) {
        out[warp*3+0] = s0 + outb[0];
        out[warp*3+1] = s1 + outb[1];
        out[warp*3+2] = s2 + outb[2];
    }
}

// ---------------- staging constants ----------------
// per-warp staging: hi buffer 16 rows x 68 uints, lo buffer same. 2176 uints/warp.
#define SROW 68
#define SWARP 2176

// load A fragments (hi+lo) for all 8 kb blocks from staging buffers
__device__ __forceinline__ void load_frags(const unsigned* bufHi, const unsigned* bufLo,
                                           int r, int t,
                                           unsigned ah[8][4], unsigned al[8][4])
{
#pragma unroll
    for (int kb = 0; kb < 8; ++kb) {
        int o0 = r * SROW + kb * 8 + t;
        int o1 = (r + 8) * SROW + kb * 8 + t;
        ah[kb][0] = bufHi[o0];     ah[kb][1] = bufHi[o1];
        ah[kb][2] = bufHi[o0 + 4]; ah[kb][3] = bufHi[o1 + 4];
        al[kb][0] = bufLo[o0];     al[kb][1] = bufLo[o1];
        al[kb][2] = bufLo[o0 + 4]; al[kb][3] = bufLo[o1 + 4];
    }
}

// 3-mma bf16 split product over one (nb) column block: acc += A * B_nb
__device__ __forceinline__ void gemm_nb(float acc[4], const unsigned ah[8][4],
                                        const unsigned al[8][4],
                                        const uint2* sW, int nb, int lane)
{
    const uint2* Bh = sW + (nb * 8) * 32 + lane;
    const uint2* Bl = Bh + 4096;
#pragma unroll
    for (int kb = 0; kb < 8; ++kb) {
        uint2 bh = Bh[kb * 32];
        uint2 bl = Bl[kb * 32];
        mma16(acc, ah[kb], bh);
        mma16(acc, al[kb], bh);
        mma16(acc, ah[kb], bl);
    }
}

// ---------------- tensor-core row GEMM ----------------
// Y = [silu]( X @ W + bias? + R? )
template<bool SILU_>
__global__ void __launch_bounds__(256, 1)
k_rowgemm_mma(const float* __restrict__ X, const unsigned* __restrict__ Wp,
              const float* __restrict__ bias, const float* __restrict__ R,
              float* __restrict__ Y, int n)
{
    extern __shared__ float smem[];
    unsigned* sW    = reinterpret_cast<unsigned*>(smem);   // WMAT uints
    float*    sBias = smem + WMAT;                          // 128
    unsigned* bufAll = reinterpret_cast<unsigned*>(smem + WMAT + 128);

    {
        const uint4* s = reinterpret_cast<const uint4*>(Wp);
        uint4* d = reinterpret_cast<uint4*>(sW);
        for (int i = threadIdx.x; i < WMAT / 4; i += 256) d[i] = s[i];
        if (threadIdx.x < H) sBias[threadIdx.x] = bias ? bias[threadIdx.x] : 0.f;
    }
    __syncthreads();

    int lane = threadIdx.x & 31;
    int warp = threadIdx.x >> 5;
    int r = lane >> 2, t = lane & 3;
    unsigned* bufHi = bufAll + warp * SWARP;
    unsigned* bufLo = bufHi + 1088;

    int nTiles = (n + 15) >> 4;
    for (int tile = blockIdx.x * 8 + warp; tile < nTiles; tile += gridDim.x * 8) {
        int row0 = tile * 16;
        // stage X tile as bf16 hi/lo
#pragma unroll
        for (int e = 0; e < 16; ++e) {
            int rw = row0 + e;
            float4 x = (rw < n) ? reinterpret_cast<const float4*>(X)[rw * H4 + lane]
                                : make_float4(0.f, 0.f, 0.f, 0.f);
            float h0,l0,h1,l1,h2,l2,h3,l3;
            bsplit(x.x,h0,l0); bsplit(x.y,h1,l1); bsplit(x.z,h2,l2); bsplit(x.w,h3,l3);
            *reinterpret_cast<uint2*>(bufHi + e * SROW + 2 * lane) = make_uint2(pbf2(h0,h1), pbf2(h2,h3));
            *reinterpret_cast<uint2*>(bufLo + e * SROW + 2 * lane) = make_uint2(pbf2(l0,l1), pbf2(l2,l3));
        }
        __syncwarp();
        unsigned ah[8][4], al[8][4];
        load_frags(bufHi, bufLo, r, t, ah, al);
        __syncwarp();

        int gr_lo = row0 + r, gr_hi = row0 + r + 8;
        bool ok_lo = gr_lo < n, ok_hi = gr_hi < n;

#pragma unroll 4
        for (int nb = 0; nb < 16; ++nb) {
            float acc[4] = {0.f, 0.f, 0.f, 0.f};
            gemm_nb(acc, ah, al, reinterpret_cast<const uint2*>(sW), nb, lane);

            int c0 = nb * 8 + 2 * t;
            float2 p = *reinterpret_cast<const float2*>(&sBias[c0]);
            float v0 = acc[0] + p.x, v1 = acc[1] + p.y;
            float v2 = acc[2] + p.x, v3 = acc[3] + p.y;
            if (R) {
                if (ok_lo) {
                    float2 r0 = *reinterpret_cast<const float2*>(&R[gr_lo * H + c0]);
                    v0 += r0.x; v1 += r0.y;
                }
                if (ok_hi) {
                    float2 r1 = *reinterpret_cast<const float2*>(&R[gr_hi * H + c0]);
                    v2 += r1.x; v3 += r1.y;
                }
            }
            if (SILU_) { v0 = silu(v0); v1 = silu(v1); v2 = silu(v2); v3 = silu(v3); }
            if (ok_lo) *reinterpret_cast<float2*>(&Y[gr_lo * H + c0]) = make_float2(v0, v1);
            if (ok_hi) *reinterpret_cast<float2*>(&Y[gr_hi * H + c0]) = make_float2(v2, v3);
        }
    }
}

// ---------------- fused edge block (tensor core, bf16x3) ----------------
__global__ void __launch_bounds__(256, 1)
k_edge_mma(const float* __restrict__ Pu, const float* __restrict__ Pv,
           const float* __restrict__ dis,
           const int* __restrict__ idu, const int* __restrict__ idv,
           const float* __restrict__ wdis, const float* __restrict__ b1,
           const unsigned* __restrict__ W2p, const float* __restrict__ b2,
           const unsigned* __restrict__ W3p, const float* __restrict__ b3,
           float* __restrict__ aOut, int E)
{
    extern __shared__ float smem[];
    unsigned* sW2 = reinterpret_cast<unsigned*>(smem);          // WMAT
    unsigned* sW3 = reinterpret_cast<unsigned*>(smem) + WMAT;   // WMAT
    float* sB2 = smem + 2 * WMAT;
    float* sB3 = smem + 2 * WMAT + 128;
    unsigned* bufAll = reinterpret_cast<unsigned*>(smem + 2 * WMAT + 256);

    {
        const uint4* s2 = reinterpret_cast<const uint4*>(W2p);
        const uint4* s3 = reinterpret_cast<const uint4*>(W3p);
        uint4* d2 = reinterpret_cast<uint4*>(sW2);
        uint4* d3 = reinterpret_cast<uint4*>(sW3);
        for (int i = threadIdx.x; i < WMAT / 4; i += 256) { d2[i] = s2[i]; d3[i] = s3[i]; }
        if (threadIdx.x < H) { sB2[threadIdx.x] = b2[threadIdx.x]; sB3[threadIdx.x] = b3[threadIdx.x]; }
    }
    __syncthreads();

    int lane = threadIdx.x & 31;
    int warp = threadIdx.x >> 5;
    int r = lane >> 2, t = lane & 3;
    unsigned* bufHi = bufAll + warp * SWARP;
    unsigned* bufLo = bufHi + 1088;
    float* scat = reinterpret_cast<float*>(bufHi);   // reused fp32 16x132 after frags loaded

    float4 wd  = reinterpret_cast<const float4*>(wdis)[lane];
    float4 bb1 = reinterpret_cast<const float4*>(b1)[lane];

    int nTiles = (E + 15) >> 4;
    for (int tile = blockIdx.x * 8 + warp; tile < nTiles; tile += gridDim.x * 8) {
        int e0 = tile * 16;
        int u_s = 0, v_s = 0; float d_s = 0.f;
        if (lane < 16 && e0 + lane < E) {
            u_s = idu[e0 + lane]; v_s = idv[e0 + lane]; d_s = dis[e0 + lane];
        }

        // ---- stage t1 = silu(Pu[u] + Pv[v] + d*Wdis + b1) as bf16 hi/lo ----
#pragma unroll
        for (int e = 0; e < 16; ++e) {
            int u = __shfl_sync(0xffffffffu, u_s, e);
            int v = __shfl_sync(0xffffffffu, v_s, e);
            float d = __shfl_sync(0xffffffffu, d_s, e);
            float4 pu = reinterpret_cast<const float4*>(Pu)[u * H4 + lane];
            float4 pv = reinterpret_cast<const float4*>(Pv)[v * H4 + lane];
            float t0 = silu(pu.x + pv.x + d * wd.x + bb1.x);
            float t1v = silu(pu.y + pv.y + d * wd.y + bb1.y);
            float t2v = silu(pu.z + pv.z + d * wd.z + bb1.z);
            float t3 = silu(pu.w + pv.w + d * wd.w + bb1.w);
            float h0,l0,h1,l1,h2,l2,h3,l3;
            bsplit(t0,h0,l0); bsplit(t1v,h1,l1); bsplit(t2v,h2,l2); bsplit(t3,h3,l3);
            *reinterpret_cast<uint2*>(bufHi + e * SROW + 2 * lane) = make_uint2(pbf2(h0,h1), pbf2(h2,h3));
            *reinterpret_cast<uint2*>(bufLo + e * SROW + 2 * lane) = make_uint2(pbf2(l0,l1), pbf2(l2,l3));
        }
        __syncwarp();
        unsigned ah[8][4], al[8][4];
        load_frags(bufHi, bufLo, r, t, ah, al);
        __syncwarp();

        // ---- GEMM1: t2 = silu(t1 @ W2 + b2) -> restage hi/lo ----
#pragma unroll 4
        for (int nb = 0; nb < 16; ++nb) {
            float acc[4] = {0.f, 0.f, 0.f, 0.f};
            gemm_nb(acc, ah, al, reinterpret_cast<const uint2*>(sW2), nb, lane);
            int c0 = nb * 8 + 2 * t;
            float2 p = *reinterpret_cast<const float2*>(&sB2[c0]);
            float v0 = silu(acc[0] + p.x), v1 = silu(acc[1] + p.y);
            float v2 = silu(acc[2] + p.x), v3 = silu(acc[3] + p.y);
            float h0,l0,h1,l1,h2,l2,h3,l3;
            bsplit(v0,h0,l0); bsplit(v1,h1,l1);
            bsplit(v2,h2,l2); bsplit(v3,h3,l3);
            bufHi[r * SROW + nb * 4 + t]       = pbf2(h0, h1);
            bufLo[r * SROW + nb * 4 + t]       = pbf2(l0, l1);
            bufHi[(r + 8) * SROW + nb * 4 + t] = pbf2(h2, h3);
            bufLo[(r + 8) * SROW + nb * 4 + t] = pbf2(l2, l3);
        }
        __syncwarp();
        load_frags(bufHi, bufLo, r, t, ah, al);
        __syncwarp();

        // ---- GEMM2: m = t2 @ W3 + b3 -> stage fp32, then red.v4 scatter ----
#pragma unroll 4
        for (int nb = 0; nb < 16; ++nb) {
            float acc[4] = {0.f, 0.f, 0.f, 0.f};
            gemm_nb(acc, ah, al, reinterpret_cast<const uint2*>(sW3), nb, lane);
            int c0 = nb * 8 + 2 * t;
            float2 q = *reinterpret_cast<const float2*>(&sB3[c0]);
            *reinterpret_cast<float2*>(&scat[r * 132 + c0])       = make_float2(acc[0] + q.x, acc[1] + q.y);
            *reinterpret_cast<float2*>(&scat[(r + 8) * 132 + c0]) = make_float2(acc[2] + q.x, acc[3] + q.y);
        }
        __syncwarp();

#pragma unroll 4
        for (int e = 0; e < 16; ++e) {
            if (e0 + e >= E) break;
            int u = __shfl_sync(0xffffffffu, u_s, e);
            int v = __shfl_sync(0xffffffffu, v_s, e);
            float4 mv = *reinterpret_cast<const float4*>(&scat[e * 132 + 4 * lane]);
            redv4(aOut + (size_t)u * H + 4 * lane, mv);
            redv4(aOut + (size_t)v * H + 4 * lane, mv);
        }
        __syncwarp();
    }
}

// ---------------- host launch ----------------
extern "C" void kernel_launch(void* const* d_in, const int* in_sizes, int n_in,
                              void* d_out, int out_size)
{
    const int*   atom = (const int*)  d_in[0];
    const float* dis1 = (const float*)d_in[1];
    const float* dis2 = (const float*)d_in[2];
    const int*   id1u = (const int*)  d_in[3];
    const int*   id1v = (const int*)  d_in[4];
    const int*   id2u = (const int*)  d_in[5];
    const int*   id2v = (const int*)  d_in[6];
    const float* emb  = (const float*)d_in[7];
    const float* Wu   = (const float*)d_in[8];
    const float* Wv   = (const float*)d_in[9];
    const float* Wdis = (const float*)d_in[10];
    const float* eb1  = (const float*)d_in[11];
    const float* eW2  = (const float*)d_in[12];
    const float* eb2  = (const float*)d_in[13];
    const float* eW3  = (const float*)d_in[14];
    const float* eb3  = (const float*)d_in[15];
    const float* Wh   = (const float*)d_in[16];
    const float* Wa1  = (const float*)d_in[17];
    const float* Wa2  = (const float*)d_in[18];
    const float* ub1  = (const float*)d_in[19];
    const float* uW2  = (const float*)d_in[20];
    const float* ub2  = (const float*)d_in[21];
    const float* outW = (const float*)d_in[22];
    const float* outb = (const float*)d_in[23];

    int n = in_sizes[0];
    int E = in_sizes[3];
    if (n > NMAX) return;

    float *h, *Pu, *Pv, *a1, *a2, *g;
    unsigned* pk;
    cudaGetSymbolAddress((void**)&h,  g_h);
    cudaGetSymbolAddress((void**)&Pu, g_Pu);
    cudaGetSymbolAddress((void**)&Pv, g_Pv);
    cudaGetSymbolAddress((void**)&a1, g_a1);
    cudaGetSymbolAddress((void**)&a2, g_a2);
    cudaGetSymbolAddress((void**)&g,  g_g);
    cudaGetSymbolAddress((void**)&pk, g_pack);

    const int SM_ROW  = (WMAT + 128 + 8 * SWARP) * 4;       // 135680 B
    const int SM_EDGE = (2 * WMAT + 256 + 8 * SWARP) * 4;   // 201728 B

    cudaFuncSetAttribute(k_rowgemm_mma<false>,
                         cudaFuncAttributeMaxDynamicSharedMemorySize, SM_ROW);
    cudaFuncSetAttribute(k_rowgemm_mma<true>,
                         cudaFuncAttributeMaxDynamicSharedMemorySize, SM_ROW);
    cudaFuncSetAttribute(k_edge_mma,
                         cudaFuncAttributeMaxDynamicSharedMemorySize, SM_EDGE);

    int gthreads = n * H4;
    int gblocks  = (gthreads + 255) / 256;

    k_pack<<<dim3(2, 24), 256>>>(Wu, Wv, eW2, eW3, Wh, Wa1, Wa2, uW2);
    k_gather<<<gblocks, 256>>>(atom, emb, h, n);

    for (int L = 0; L < 2; ++L) {
        k_zero2<<<gblocks, 256>>>(a1, a2, n * H4);

        int i1 = 2 * L, i2 = 2 * L + 1;

        // edge block i1 (graph 1) -> a1
        k_rowgemm_mma<false><<<148, 256, SM_ROW>>>(h, pk + (0 + i1) * WMAT, 0, 0, Pu, n);
        k_rowgemm_mma<false><<<148, 256, SM_ROW>>>(h, pk + (4 + i1) * WMAT, 0, 0, Pv, n);
        k_edge_mma<<<148, 256, SM_EDGE>>>(
            Pu, Pv, dis1, id1u, id1v,
            Wdis + i1 * H, eb1 + i1 * H,
            pk + (8 + i1) * WMAT, eb2 + i1 * H,
            pk + (12 + i1) * WMAT, eb3 + i1 * H, a1, E);

        // edge block i2 (graph 2) -> a2
        k_rowgemm_mma<false><<<148, 256, SM_ROW>>>(h, pk + (0 + i2) * WMAT, 0, 0, Pu, n);
        k_rowgemm_mma<false><<<148, 256, SM_ROW>>>(h, pk + (4 + i2) * WMAT, 0, 0, Pv, n);
        k_edge_mma<<<148, 256, SM_EDGE>>>(
            Pu, Pv, dis2, id2u, id2v,
            Wdis + i2 * H, eb1 + i2 * H,
            pk + (8 + i2) * WMAT, eb2 + i2 * H,
            pk + (12 + i2) * WMAT, eb3 + i2 * H, a2, E);

        // atom update L:
        //   g = h @ Wh ; g += a1 @ Wa1 ; g = silu(g + a2 @ Wa2 + ub1)
        //   h = g @ uW2 + ub2 + h
        k_rowgemm_mma<false><<<148, 256, SM_ROW>>>(h,  pk + (16 + L) * WMAT, 0,           0, g, n);
        k_rowgemm_mma<false><<<148, 256, SM_ROW>>>(a1, pk + (18 + L) * WMAT, 0,           g, g, n);
        k_rowgemm_mma<true ><<<148, 256, SM_ROW>>>(a2, pk + (20 + L) * WMAT, ub1 + L * H, g, g, n);
        k_rowgemm_mma<false><<<148, 256, SM_ROW>>>(g,  pk + (22 + L) * WMAT, ub2 + L * H, h, h, n);
    }

    k_out<<<gblocks, 256>>>(h, outW, outb, (float*)d_out, n);
}

// round 7
// speedup vs baseline: 4.0349x; 1.1895x over previous
#include <cuda_runtime.h>
#include <cuda_bf16.h>
#include <math.h>

#define H 128
#define H4 32
#define NMAX 50176
#define WMAT 16384   // packed weight footprint in unsigneds per matrix (hi+lo)

// ---------------- device scratch (static, no allocation) ----------------
__device__ float g_h [NMAX * H];
__device__ float g_Pu[NMAX * H];
__device__ float g_Pv[NMAX * H];
__device__ float g_a1[NMAX * H];
__device__ float g_a2[NMAX * H];
__device__ float g_g [NMAX * H];
__device__ unsigned g_pack[24 * WMAT];   // bf16 hi/lo fragment-packed weights

// ---------------- helpers ----------------
__device__ __forceinline__ float silu(float x) { return x / (1.0f + __expf(-x)); }

// pack two floats to bf16x2: low half = a, high half = b
__device__ __forceinline__ unsigned pbf2(float a, float b) {
    unsigned r;
    asm("cvt.rn.bf16x2.f32 %0, %1, %2;" : "=r"(r) : "f"(b), "f"(a));
    return r;
}

// split x into bf16 hi + fp32 residual
__device__ __forceinline__ void bsplit(float x, float& hi, float& lo) {
    __nv_bfloat16 h = __float2bfloat16(x);
    hi = __bfloat162float(h);
    lo = x - hi;
}

// m16n8k16 bf16 mma, D += A*B
__device__ __forceinline__ void mma16(float* c, const unsigned* a, uint2 b) {
    asm volatile(
        "mma.sync.aligned.m16n8k16.row.col.f32.bf16.bf16.f32 "
        "{%0,%1,%2,%3},{%4,%5,%6,%7},{%8,%9},{%0,%1,%2,%3};"
        : "+f"(c[0]), "+f"(c[1]), "+f"(c[2]), "+f"(c[3])
        : "r"(a[0]), "r"(a[1]), "r"(a[2]), "r"(a[3]), "r"(b.x), "r"(b.y));
}

// vectorized reduction atomic: aOut[0..3] += v
__device__ __forceinline__ void redv4(float* p, float4 v) {
    asm volatile("red.global.add.v4.f32 [%0], {%1,%2,%3,%4};"
                 :: "l"(p), "f"(v.x), "f"(v.y), "f"(v.z), "f"(v.w) : "memory");
}

// ---------------- weight packing ----------------
// For each matrix (128x128 row-major fp32), build m16n8k16 B-fragments
// (B col-major K x N) for hi and lo bf16 splits:
//   per (nb 0..15, kb 0..7, lane): uint2 { {B[k0][n],B[k0+1][n]}, {B[k0+8][n],B[k0+9][n]} }
//   k0 = kb*16 + 2*(lane&3), n = nb*8 + (lane>>2)
__global__ void k_pack(const float* __restrict__ Wu,  const float* __restrict__ Wv,
                       const float* __restrict__ eW2, const float* __restrict__ eW3,
                       const float* __restrict__ Wh,  const float* __restrict__ Wa1,
                       const float* __restrict__ Wa2, const float* __restrict__ uW2)
{
    int m = blockIdx.y;
    const float* src;
    if      (m < 4)  src = Wu  + m * H * H;
    else if (m < 8)  src = Wv  + (m - 4) * H * H;
    else if (m < 12) src = eW2 + (m - 8) * H * H;
    else if (m < 16) src = eW3 + (m - 12) * H * H;
    else if (m < 18) src = Wh  + (m - 16) * H * H;
    else if (m < 20) src = Wa1 + (m - 18) * H * H;
    else if (m < 22) src = Wa2 + (m - 20) * H * H;
    else             src = uW2 + (m - 22) * H * H;

    uint2* dhi = reinterpret_cast<uint2*>(g_pack + m * WMAT);
    uint2* dlo = dhi + 4096;

    for (int idx = blockIdx.x * blockDim.x + threadIdx.x; idx < 4096;
         idx += gridDim.x * blockDim.x) {
        int lane = idx & 31, kbnb = idx >> 5;
        int t = lane & 3, g = lane >> 2;
        int kb = kbnb & 7, nb = kbnb >> 3;
        int k0 = kb * 16 + 2 * t;
        int n  = nb * 8 + g;
        float w0 = src[(k0    ) * H + n];
        float w1 = src[(k0 + 1) * H + n];
        float w8 = src[(k0 + 8) * H + n];
        float w9 = src[(k0 + 9) * H + n];
        float h0, l0, h1, l1, h8, l8, h9, l9;
        bsplit(w0, h0, l0); bsplit(w1, h1, l1);
        bsplit(w8, h8, l8); bsplit(w9, h9, l9);
        dhi[idx] = make_uint2(pbf2(h0, h1), pbf2(h8, h9));
        dlo[idx] = make_uint2(pbf2(l0, l1), pbf2(l8, l9));
    }
}

// ---------------- misc kernels ----------------
__global__ void k_gather(const int* __restrict__ atom,
                         const float* __restrict__ emb,
                         float* __restrict__ h, int n)
{
    int i = blockIdx.x * blockDim.x + threadIdx.x;
    if (i >= n * H4) return;
    int row = i >> 5, col = i & 31;
    reinterpret_cast<float4*>(h)[i] =
        reinterpret_cast<const float4*>(emb)[atom[row] * H4 + col];
}

__global__ void k_zero2(float* __restrict__ a, float* __restrict__ b, int n4)
{
    int i = blockIdx.x * blockDim.x + threadIdx.x;
    if (i >= n4) return;
    float4 z = make_float4(0.f, 0.f, 0.f, 0.f);
    reinterpret_cast<float4*>(a)[i] = z;
    reinterpret_cast<float4*>(b)[i] = z;
}

__global__ void k_out(const float* __restrict__ h,
                      const float* __restrict__ outW,
                      const float* __restrict__ outb,
                      float* __restrict__ out, int n)
{
    int warp = (blockIdx.x * blockDim.x + threadIdx.x) >> 5;
    int lane = threadIdx.x & 31;
    if (warp >= n) return;
    float4 x = reinterpret_cast<const float4*>(h)[warp * H4 + lane];
    int k0 = lane * 4;
    float s0 = x.x * outW[(k0+0)*3+0] + x.y * outW[(k0+1)*3+0]
             + x.z * outW[(k0+2)*3+0] + x.w * outW[(k0+3)*3+0];
    float s1 = x.x * outW[(k0+0)*3+1] + x.y * outW[(k0+1)*3+1]
             + x.z * outW[(k0+2)*3+1] + x.w * outW[(k0+3)*3+1];
    float s2 = x.x * outW[(k0+0)*3+2] + x.y * outW[(k0+1)*3+2]
             + x.z * outW[(k0+2)*3+2] + x.w * outW[(k0+3)*3+2];
#pragma unroll
    for (int off = 16; off; off >>= 1) {
        s0 += __shfl_xor_sync(0xffffffffu, s0, off);
        s1 += __shfl_xor_sync(0xffffffffu, s1, off);
        s2 += __shfl_xor_sync(0xffffffffu, s2, off);
    }
    if (lane == 0) {
        out[warp*3+0] = s0 + outb[0];
        out[warp*3+1] = s1 + outb[1];
        out[warp*3+2] = s2 + outb[2];
    }
}

// ---------------- staging constants ----------------
// per-warp staging: hi buffer 16 rows x 68 uints, lo buffer same. 2176 uints/warp.
#define SROW 68
#define SWARP 2176
#define EDGE_WARPS 10
#define ROW_WARPS 16

// load A fragments (hi+lo) for all 8 kb blocks from staging buffers
__device__ __forceinline__ void load_frags(const unsigned* bufHi, const unsigned* bufLo,
                                           int r, int t,
                                           unsigned ah[8][4], unsigned al[8][4])
{
#pragma unroll
    for (int kb = 0; kb < 8; ++kb) {
        int o0 = r * SROW + kb * 8 + t;
        int o1 = (r + 8) * SROW + kb * 8 + t;
        ah[kb][0] = bufHi[o0];     ah[kb][1] = bufHi[o1];
        ah[kb][2] = bufHi[o0 + 4]; ah[kb][3] = bufHi[o1 + 4];
        al[kb][0] = bufLo[o0];     al[kb][1] = bufLo[o1];
        al[kb][2] = bufLo[o0 + 4]; al[kb][3] = bufLo[o1 + 4];
    }
}

// 3-mma bf16 split product over one (nb) column block: acc += A * B_nb
__device__ __forceinline__ void gemm_nb(float acc[4], const unsigned ah[8][4],
                                        const unsigned al[8][4],
                                        const uint2* sW, int nb, int lane)
{
    const uint2* Bh = sW + (nb * 8) * 32 + lane;
    const uint2* Bl = Bh + 4096;
#pragma unroll
    for (int kb = 0; kb < 8; ++kb) {
        uint2 bh = Bh[kb * 32];
        uint2 bl = Bl[kb * 32];
        mma16(acc, ah[kb], bh);
        mma16(acc, al[kb], bh);
        mma16(acc, ah[kb], bl);
    }
}

// ---------------- tensor-core row GEMM ----------------
// Y = [silu]( X @ W + bias? + R? )
template<bool SILU_>
__global__ void __launch_bounds__(ROW_WARPS * 32, 1)
k_rowgemm_mma(const float* __restrict__ X, const unsigned* __restrict__ Wp,
              const float* __restrict__ bias, const float* __restrict__ R,
              float* __restrict__ Y, int n)
{
    extern __shared__ float smem[];
    unsigned* sW    = reinterpret_cast<unsigned*>(smem);   // WMAT uints
    float*    sBias = smem + WMAT;                          // 128
    unsigned* bufAll = reinterpret_cast<unsigned*>(smem + WMAT + 128);

    {
        const uint4* s = reinterpret_cast<const uint4*>(Wp);
        uint4* d = reinterpret_cast<uint4*>(sW);
        for (int i = threadIdx.x; i < WMAT / 4; i += ROW_WARPS * 32) d[i] = s[i];
        if (threadIdx.x < H) sBias[threadIdx.x] = bias ? bias[threadIdx.x] : 0.f;
    }
    __syncthreads();

    int lane = threadIdx.x & 31;
    int warp = threadIdx.x >> 5;
    int r = lane >> 2, t = lane & 3;
    unsigned* bufHi = bufAll + warp * SWARP;
    unsigned* bufLo = bufHi + 1088;

    int nTiles = (n + 15) >> 4;
    for (int tile = blockIdx.x * ROW_WARPS + warp; tile < nTiles;
         tile += gridDim.x * ROW_WARPS) {
        int row0 = tile * 16;
        // stage X tile as bf16 hi/lo
#pragma unroll
        for (int e = 0; e < 16; ++e) {
            int rw = row0 + e;
            float4 x = (rw < n) ? reinterpret_cast<const float4*>(X)[rw * H4 + lane]
                                : make_float4(0.f, 0.f, 0.f, 0.f);
            float h0,l0,h1,l1,h2,l2,h3,l3;
            bsplit(x.x,h0,l0); bsplit(x.y,h1,l1); bsplit(x.z,h2,l2); bsplit(x.w,h3,l3);
            *reinterpret_cast<uint2*>(bufHi + e * SROW + 2 * lane) = make_uint2(pbf2(h0,h1), pbf2(h2,h3));
            *reinterpret_cast<uint2*>(bufLo + e * SROW + 2 * lane) = make_uint2(pbf2(l0,l1), pbf2(l2,l3));
        }
        __syncwarp();
        unsigned ah[8][4], al[8][4];
        load_frags(bufHi, bufLo, r, t, ah, al);
        __syncwarp();

        int gr_lo = row0 + r, gr_hi = row0 + r + 8;
        bool ok_lo = gr_lo < n, ok_hi = gr_hi < n;

#pragma unroll 4
        for (int nb = 0; nb < 16; ++nb) {
            float acc[4] = {0.f, 0.f, 0.f, 0.f};
            gemm_nb(acc, ah, al, reinterpret_cast<const uint2*>(sW), nb, lane);

            int c0 = nb * 8 + 2 * t;
            float2 p = *reinterpret_cast<const float2*>(&sBias[c0]);
            float v0 = acc[0] + p.x, v1 = acc[1] + p.y;
            float v2 = acc[2] + p.x, v3 = acc[3] + p.y;
            if (R) {
                if (ok_lo) {
                    float2 r0 = *reinterpret_cast<const float2*>(&R[gr_lo * H + c0]);
                    v0 += r0.x; v1 += r0.y;
                }
                if (ok_hi) {
                    float2 r1 = *reinterpret_cast<const float2*>(&R[gr_hi * H + c0]);
                    v2 += r1.x; v3 += r1.y;
                }
            }
            if (SILU_) { v0 = silu(v0); v1 = silu(v1); v2 = silu(v2); v3 = silu(v3); }
            if (ok_lo) *reinterpret_cast<float2*>(&Y[gr_lo * H + c0]) = make_float2(v0, v1);
            if (ok_hi) *reinterpret_cast<float2*>(&Y[gr_hi * H + c0]) = make_float2(v2, v3);
        }
    }
}

// ---------------- fused edge block (tensor core, bf16x3) ----------------
// GEMM1 output fragments ARE the GEMM2 input fragments (C-layout at
// nb=2kb,2kb+1 == A-layout at kb), so no smem restage between GEMMs.
__global__ void __launch_bounds__(EDGE_WARPS * 32, 1)
k_edge_mma(const float* __restrict__ Pu, const float* __restrict__ Pv,
           const float* __restrict__ dis,
           const int* __restrict__ idu, const int* __restrict__ idv,
           const float* __restrict__ wdis, const float* __restrict__ b1,
           const unsigned* __restrict__ W2p, const float* __restrict__ b2,
           const unsigned* __restrict__ W3p, const float* __restrict__ b3,
           float* __restrict__ aOut, int E)
{
    extern __shared__ float smem[];
    unsigned* sW2 = reinterpret_cast<unsigned*>(smem);          // WMAT
    unsigned* sW3 = reinterpret_cast<unsigned*>(smem) + WMAT;   // WMAT
    float* sB2 = smem + 2 * WMAT;
    float* sB3 = smem + 2 * WMAT + 128;
    unsigned* bufAll = reinterpret_cast<unsigned*>(smem + 2 * WMAT + 256);

    {
        const uint4* s2 = reinterpret_cast<const uint4*>(W2p);
        const uint4* s3 = reinterpret_cast<const uint4*>(W3p);
        uint4* d2 = reinterpret_cast<uint4*>(sW2);
        uint4* d3 = reinterpret_cast<uint4*>(sW3);
        for (int i = threadIdx.x; i < WMAT / 4; i += EDGE_WARPS * 32) { d2[i] = s2[i]; d3[i] = s3[i]; }
        if (threadIdx.x < H) { sB2[threadIdx.x] = b2[threadIdx.x]; sB3[threadIdx.x] = b3[threadIdx.x]; }
    }
    __syncthreads();

    int lane = threadIdx.x & 31;
    int warp = threadIdx.x >> 5;
    int r = lane >> 2, t = lane & 3;
    unsigned* bufHi = bufAll + warp * SWARP;
    unsigned* bufLo = bufHi + 1088;
    float* scat = reinterpret_cast<float*>(bufHi);   // fp32 16x132, reused after frag load

    float4 wd  = reinterpret_cast<const float4*>(wdis)[lane];
    float4 bb1 = reinterpret_cast<const float4*>(b1)[lane];

    int nTiles = (E + 15) >> 4;
    for (int tile = blockIdx.x * EDGE_WARPS + warp; tile < nTiles;
         tile += gridDim.x * EDGE_WARPS) {
        int e0 = tile * 16;
        int u_s = 0, v_s = 0; float d_s = 0.f;
        if (lane < 16 && e0 + lane < E) {
            u_s = idu[e0 + lane]; v_s = idv[e0 + lane]; d_s = dis[e0 + lane];
        }

        // ---- stage t1 = silu(Pu[u] + Pv[v] + d*Wdis + b1) as bf16 hi/lo ----
#pragma unroll
        for (int e = 0; e < 16; ++e) {
            int u = __shfl_sync(0xffffffffu, u_s, e);
            int v = __shfl_sync(0xffffffffu, v_s, e);
            float d = __shfl_sync(0xffffffffu, d_s, e);
            float4 pu = reinterpret_cast<const float4*>(Pu)[u * H4 + lane];
            float4 pv = reinterpret_cast<const float4*>(Pv)[v * H4 + lane];
            float t0 = silu(pu.x + pv.x + d * wd.x + bb1.x);
            float t1v = silu(pu.y + pv.y + d * wd.y + bb1.y);
            float t2v = silu(pu.z + pv.z + d * wd.z + bb1.z);
            float t3 = silu(pu.w + pv.w + d * wd.w + bb1.w);
            float h0,l0,h1,l1,h2,l2,h3,l3;
            bsplit(t0,h0,l0); bsplit(t1v,h1,l1); bsplit(t2v,h2,l2); bsplit(t3,h3,l3);
            *reinterpret_cast<uint2*>(bufHi + e * SROW + 2 * lane) = make_uint2(pbf2(h0,h1), pbf2(h2,h3));
            *reinterpret_cast<uint2*>(bufLo + e * SROW + 2 * lane) = make_uint2(pbf2(l0,l1), pbf2(l2,l3));
        }
        __syncwarp();
        unsigned ah[8][4], al[8][4];
        load_frags(bufHi, bufLo, r, t, ah, al);
        __syncwarp();

        // ---- GEMM1: t2 = silu(t1 @ W2 + b2), outputs become GEMM2 A-frags ----
        unsigned bh[8][4], bl[8][4];
#pragma unroll
        for (int kb = 0; kb < 8; ++kb) {
#pragma unroll
            for (int s = 0; s < 2; ++s) {
                int nb = 2 * kb + s;
                float acc[4] = {0.f, 0.f, 0.f, 0.f};
                gemm_nb(acc, ah, al, reinterpret_cast<const uint2*>(sW2), nb, lane);
                int c0 = nb * 8 + 2 * t;
                float2 p = *reinterpret_cast<const float2*>(&sB2[c0]);
                float v0 = silu(acc[0] + p.x), v1 = silu(acc[1] + p.y);
                float v2 = silu(acc[2] + p.x), v3 = silu(acc[3] + p.y);
                float h0,l0,h1,l1,h2,l2,h3,l3;
                bsplit(v0,h0,l0); bsplit(v1,h1,l1);
                bsplit(v2,h2,l2); bsplit(v3,h3,l3);
                bh[kb][2*s]     = pbf2(h0, h1);  bl[kb][2*s]     = pbf2(l0, l1);
                bh[kb][2*s + 1] = pbf2(h2, h3);  bl[kb][2*s + 1] = pbf2(l2, l3);
            }
        }

        // ---- GEMM2: m = t2 @ W3 + b3 -> stage fp32, then red.v4 scatter ----
#pragma unroll 4
        for (int nb = 0; nb < 16; ++nb) {
            float acc[4] = {0.f, 0.f, 0.f, 0.f};
            gemm_nb(acc, bh, bl, reinterpret_cast<const uint2*>(sW3), nb, lane);
            int c0 = nb * 8 + 2 * t;
            float2 q = *reinterpret_cast<const float2*>(&sB3[c0]);
            *reinterpret_cast<float2*>(&scat[r * 132 + c0])       = make_float2(acc[0] + q.x, acc[1] + q.y);
            *reinterpret_cast<float2*>(&scat[(r + 8) * 132 + c0]) = make_float2(acc[2] + q.x, acc[3] + q.y);
        }
        __syncwarp();

#pragma unroll 4
        for (int e = 0; e < 16; ++e) {
            if (e0 + e >= E) break;
            int u = __shfl_sync(0xffffffffu, u_s, e);
            int v = __shfl_sync(0xffffffffu, v_s, e);
            float4 mv = *reinterpret_cast<const float4*>(&scat[e * 132 + 4 * lane]);
            redv4(aOut + (size_t)u * H + 4 * lane, mv);
            redv4(aOut + (size_t)v * H + 4 * lane, mv);
        }
        __syncwarp();
    }
}

// ---------------- host launch ----------------
extern "C" void kernel_launch(void* const* d_in, const int* in_sizes, int n_in,
                              void* d_out, int out_size)
{
    const int*   atom = (const int*)  d_in[0];
    const float* dis1 = (const float*)d_in[1];
    const float* dis2 = (const float*)d_in[2];
    const int*   id1u = (const int*)  d_in[3];
    const int*   id1v = (const int*)  d_in[4];
    const int*   id2u = (const int*)  d_in[5];
    const int*   id2v = (const int*)  d_in[6];
    const float* emb  = (const float*)d_in[7];
    const float* Wu   = (const float*)d_in[8];
    const float* Wv   = (const float*)d_in[9];
    const float* Wdis = (const float*)d_in[10];
    const float* eb1  = (const float*)d_in[11];
    const float* eW2  = (const float*)d_in[12];
    const float* eb2  = (const float*)d_in[13];
    const float* eW3  = (const float*)d_in[14];
    const float* eb3  = (const float*)d_in[15];
    const float* Wh   = (const float*)d_in[16];
    const float* Wa1  = (const float*)d_in[17];
    const float* Wa2  = (const float*)d_in[18];
    const float* ub1  = (const float*)d_in[19];
    const float* uW2  = (const float*)d_in[20];
    const float* ub2  = (const float*)d_in[21];
    const float* outW = (const float*)d_in[22];
    const float* outb = (const float*)d_in[23];

    int n = in_sizes[0];
    int E = in_sizes[3];
    if (n > NMAX) return;

    float *h, *Pu, *Pv, *a1, *a2, *g;
    unsigned* pk;
    cudaGetSymbolAddress((void**)&h,  g_h);
    cudaGetSymbolAddress((void**)&Pu, g_Pu);
    cudaGetSymbolAddress((void**)&Pv, g_Pv);
    cudaGetSymbolAddress((void**)&a1, g_a1);
    cudaGetSymbolAddress((void**)&a2, g_a2);
    cudaGetSymbolAddress((void**)&g,  g_g);
    cudaGetSymbolAddress((void**)&pk, g_pack);

    const int SM_ROW  = (WMAT + 128) * 4 + ROW_WARPS * SWARP * 4;    // 205312 B
    const int SM_EDGE = (2 * WMAT + 256) * 4 + EDGE_WARPS * SWARP * 4; // 219136 B

    cudaFuncSetAttribute(k_rowgemm_mma<false>,
                         cudaFuncAttributeMaxDynamicSharedMemorySize, SM_ROW);
    cudaFuncSetAttribute(k_rowgemm_mma<true>,
                         cudaFuncAttributeMaxDynamicSharedMemorySize, SM_ROW);
    cudaFuncSetAttribute(k_edge_mma,
                         cudaFuncAttributeMaxDynamicSharedMemorySize, SM_EDGE);

    int gthreads = n * H4;
    int gblocks  = (gthreads + 255) / 256;

    k_pack<<<dim3(2, 24), 256>>>(Wu, Wv, eW2, eW3, Wh, Wa1, Wa2, uW2);
    k_gather<<<gblocks, 256>>>(atom, emb, h, n);

    for (int L = 0; L < 2; ++L) {
        k_zero2<<<gblocks, 256>>>(a1, a2, n * H4);

        int i1 = 2 * L, i2 = 2 * L + 1;

        // edge block i1 (graph 1) -> a1
        k_rowgemm_mma<false><<<148, ROW_WARPS * 32, SM_ROW>>>(h, pk + (0 + i1) * WMAT, 0, 0, Pu, n);
        k_rowgemm_mma<false><<<148, ROW_WARPS * 32, SM_ROW>>>(h, pk + (4 + i1) * WMAT, 0, 0, Pv, n);
        k_edge_mma<<<148, EDGE_WARPS * 32, SM_EDGE>>>(
            Pu, Pv, dis1, id1u, id1v,
            Wdis + i1 * H, eb1 + i1 * H,
            pk + (8 + i1) * WMAT, eb2 + i1 * H,
            pk + (12 + i1) * WMAT, eb3 + i1 * H, a1, E);

        // edge block i2 (graph 2) -> a2
        k_rowgemm_mma<false><<<148, ROW_WARPS * 32, SM_ROW>>>(h, pk + (0 + i2) * WMAT, 0, 0, Pu, n);
        k_rowgemm_mma<false><<<148, ROW_WARPS * 32, SM_ROW>>>(h, pk + (4 + i2) * WMAT, 0, 0, Pv, n);
        k_edge_mma<<<148, EDGE_WARPS * 32, SM_EDGE>>>(
            Pu, Pv, dis2, id2u, id2v,
            Wdis + i2 * H, eb1 + i2 * H,
            pk + (8 + i2) * WMAT, eb2 + i2 * H,
            pk + (12 + i2) * WMAT, eb3 + i2 * H, a2, E);

        // atom update L:
        //   g = h @ Wh ; g += a1 @ Wa1 ; g = silu(g + a2 @ Wa2 + ub1)
        //   h = g @ uW2 + ub2 + h
        k_rowgemm_mma<false><<<148, ROW_WARPS * 32, SM_ROW>>>(h,  pk + (16 + L) * WMAT, 0,           0, g, n);
        k_rowgemm_mma<false><<<148, ROW_WARPS * 32, SM_ROW>>>(a1, pk + (18 + L) * WMAT, 0,           g, g, n);
        k_rowgemm_mma<true ><<<148, ROW_WARPS * 32, SM_ROW>>>(a2, pk + (20 + L) * WMAT, ub1 + L * H, g, g, n);
        k_rowgemm_mma<false><<<148, ROW_WARPS * 32, SM_ROW>>>(g,  pk + (22 + L) * WMAT, ub2 + L * H, h, h, n);
    }

    k_out<<<gblocks, 256>>>(h, outW, outb, (float*)d_out, n);
}

// round 10
// speedup vs baseline: 4.2408x; 1.0510x over previous
#include <cuda_runtime.h>
#include <cuda_bf16.h>
#include <stdint.h>
#include <math.h>

#define H 128
#define H4 32
#define NMAX 50176
#define WMAT 16384   // packed weight footprint in unsigneds per matrix (hi+lo)

// ---------------- device scratch (static, no allocation) ----------------
__device__ float g_h [NMAX * H];
__device__ float g_Pu[NMAX * H];
__device__ float g_Pv[NMAX * H];
__device__ float g_a1[NMAX * H];
__device__ float g_a2[NMAX * H];
__device__ float g_g [NMAX * H];
__device__ unsigned g_pack[24 * WMAT];   // bf16 hi/lo fragment-packed weights

// ---------------- helpers ----------------
__device__ __forceinline__ float silu(float x) { return x / (1.0f + __expf(-x)); }

// pack two floats to bf16x2: low half = a, high half = b
__device__ __forceinline__ unsigned pbf2(float a, float b) {
    unsigned r;
    asm("cvt.rn.bf16x2.f32 %0, %1, %2;" : "=r"(r) : "f"(b), "f"(a));
    return r;
}

// split x into bf16 hi + fp32 residual
__device__ __forceinline__ void bsplit(float x, float& hi, float& lo) {
    __nv_bfloat16 h = __float2bfloat16(x);
    hi = __bfloat162float(h);
    lo = x - hi;
}

// m16n8k16 bf16 mma, D += A*B
__device__ __forceinline__ void mma16(float* c, const unsigned* a, uint2 b) {
    asm volatile(
        "mma.sync.aligned.m16n8k16.row.col.f32.bf16.bf16.f32 "
        "{%0,%1,%2,%3},{%4,%5,%6,%7},{%8,%9},{%0,%1,%2,%3};"
        : "+f"(c[0]), "+f"(c[1]), "+f"(c[2]), "+f"(c[3])
        : "r"(a[0]), "r"(a[1]), "r"(a[2]), "r"(a[3]), "r"(b.x), "r"(b.y));
}

// vectorized reduction atomic: p[0..3] += v
__device__ __forceinline__ void redv4(float* p, float4 v) {
    asm volatile("red.global.add.v4.f32 [%0], {%1,%2,%3,%4};"
                 :: "l"(p), "f"(v.x), "f"(v.y), "f"(v.z), "f"(v.w) : "memory");
}

// ---------------- weight packing ----------------
// For each matrix (128x128 row-major fp32), build m16n8k16 B-fragments
// (B col-major K x N) for hi and lo bf16 splits:
//   per (nb 0..15, kb 0..7, lane): uint2 { {B[k0][n],B[k0+1][n]}, {B[k0+8][n],B[k0+9][n]} }
//   k0 = kb*16 + 2*(lane&3), n = nb*8 + (lane>>2)
__global__ void k_pack(const float* __restrict__ Wu,  const float* __restrict__ Wv,
                       const float* __restrict__ eW2, const float* __restrict__ eW3,
                       const float* __restrict__ Wh,  const float* __restrict__ Wa1,
                       const float* __restrict__ Wa2, const float* __restrict__ uW2)
{
    int m = blockIdx.y;
    const float* src;
    if      (m < 4)  src = Wu  + m * H * H;
    else if (m < 8)  src = Wv  + (m - 4) * H * H;
    else if (m < 12) src = eW2 + (m - 8) * H * H;
    else if (m < 16) src = eW3 + (m - 12) * H * H;
    else if (m < 18) src = Wh  + (m - 16) * H * H;
    else if (m < 20) src = Wa1 + (m - 18) * H * H;
    else if (m < 22) src = Wa2 + (m - 20) * H * H;
    else             src = uW2 + (m - 22) * H * H;

    uint2* dhi = reinterpret_cast<uint2*>(g_pack + m * WMAT);
    uint2* dlo = dhi + 4096;

    for (int idx = blockIdx.x * blockDim.x + threadIdx.x; idx < 4096;
         idx += gridDim.x * blockDim.x) {
        int lane = idx & 31, kbnb = idx >> 5;
        int t = lane & 3, g = lane >> 2;
        int kb = kbnb & 7, nb = kbnb >> 3;
        int k0 = kb * 16 + 2 * t;
        int n  = nb * 8 + g;
        float w0 = src[(k0    ) * H + n];
        float w1 = src[(k0 + 1) * H + n];
        float w8 = src[(k0 + 8) * H + n];
        float w9 = src[(k0 + 9) * H + n];
        float h0, l0, h1, l1, h8, l8, h9, l9;
        bsplit(w0, h0, l0); bsplit(w1, h1, l1);
        bsplit(w8, h8, l8); bsplit(w9, h9, l9);
        dhi[idx] = make_uint2(pbf2(h0, h1), pbf2(h8, h9));
        dlo[idx] = make_uint2(pbf2(l0, l1), pbf2(l8, l9));
    }
}

// ---------------- misc kernels ----------------
__global__ void k_gather(const int* __restrict__ atom,
                         const float* __restrict__ emb,
                         float* __restrict__ h, int n)
{
    int i = blockIdx.x * blockDim.x + threadIdx.x;
    if (i >= n * H4) return;
    int row = i >> 5, col = i & 31;
    reinterpret_cast<float4*>(h)[i] =
        reinterpret_cast<const float4*>(emb)[atom[row] * H4 + col];
}

__global__ void k_zero2(float* __restrict__ a, float* __restrict__ b, int n4)
{
    int i = blockIdx.x * blockDim.x + threadIdx.x;
    if (i >= n4) return;
    float4 z = make_float4(0.f, 0.f, 0.f, 0.f);
    reinterpret_cast<float4*>(a)[i] = z;
    reinterpret_cast<float4*>(b)[i] = z;
}

__global__ void k_out(const float* __restrict__ h,
                      const float* __restrict__ outW,
                      const float* __restrict__ outb,
                      float* __restrict__ out, int n)
{
    int warp = (blockIdx.x * blockDim.x + threadIdx.x) >> 5;
    int lane = threadIdx.x & 31;
    if (warp >= n) return;
    float4 x = reinterpret_cast<const float4*>(h)[warp * H4 + lane];
    int k0 = lane * 4;
    float s0 = x.x * outW[(k0+0)*3+0] + x.y * outW[(k0+1)*3+0]
             + x.z * outW[(k0+2)*3+0] + x.w * outW[(k0+3)*3+0];
    float s1 = x.x * outW[(k0+0)*3+1] + x.y * outW[(k0+1)*3+1]
             + x.z * outW[(k0+2)*3+1] + x.w * outW[(k0+3)*3+1];
    float s2 = x.x * outW[(k0+0)*3+2] + x.y * outW[(k0+1)*3+2]
             + x.z * outW[(k0+2)*3+2] + x.w * outW[(k0+3)*3+2];
#pragma unroll
    for (int off = 16; off; off >>= 1) {
        s0 += __shfl_xor_sync(0xffffffffu, s0, off);
        s1 += __shfl_xor_sync(0xffffffffu, s1, off);
        s2 += __shfl_xor_sync(0xffffffffu, s2, off);
    }
    if (lane == 0) {
        out[warp*3+0] = s0 + outb[0];
        out[warp*3+1] = s1 + outb[1];
        out[warp*3+2] = s2 + outb[2];
    }
}

// ---------------- staging constants ----------------
// per-warp staging: hi buffer 16 rows x 68 uints, lo buffer same. 2176 uints/warp.
#define SROW 68
#define SWARP 2176
#define EDGE_WARPS 10
#define ROW_WARPS 16
#define ROW2_WARPS 10

// load A fragments (hi+lo) for all 8 kb blocks from staging buffers
__device__ __forceinline__ void load_frags(const unsigned* bufHi, const unsigned* bufLo,
                                           int r, int t,
                                           unsigned ah[8][4], unsigned al[8][4])
{
#pragma unroll
    for (int kb = 0; kb < 8; ++kb) {
        int o0 = r * SROW + kb * 8 + t;
        int o1 = (r + 8) * SROW + kb * 8 + t;
        ah[kb][0] = bufHi[o0];     ah[kb][1] = bufHi[o1];
        ah[kb][2] = bufHi[o0 + 4]; ah[kb][3] = bufHi[o1 + 4];
        al[kb][0] = bufLo[o0];     al[kb][1] = bufLo[o1];
        al[kb][2] = bufLo[o0 + 4]; al[kb][3] = bufLo[o1 + 4];
    }
}

// 3-mma bf16 split product over one (nb) column block: acc += A * B_nb
__device__ __forceinline__ void gemm_nb(float acc[4], const unsigned ah[8][4],
                                        const unsigned al[8][4],
                                        const uint2* sW, int nb, int lane)
{
    const uint2* Bh = sW + (nb * 8) * 32 + lane;
    const uint2* Bl = Bh + 4096;
#pragma unroll
    for (int kb = 0; kb < 8; ++kb) {
        uint2 bh = Bh[kb * 32];
        uint2 bl = Bl[kb * 32];
        mma16(acc, ah[kb], bh);
        mma16(acc, al[kb], bh);
        mma16(acc, ah[kb], bl);
    }
}

// ---------------- tensor-core row GEMM ----------------
// Y = [silu]( X @ W + bias? + R? )
template<bool SILU_>
__global__ void __launch_bounds__(ROW_WARPS * 32, 1)
k_rowgemm_mma(const float* __restrict__ X, const unsigned* __restrict__ Wp,
              const float* __restrict__ bias, const float* __restrict__ R,
              float* __restrict__ Y, int n)
{
    extern __shared__ float smem[];
    unsigned* sW    = reinterpret_cast<unsigned*>(smem);
    float*    sBias = smem + WMAT;
    unsigned* bufAll = reinterpret_cast<unsigned*>(smem + WMAT + 128);

    {
        const uint4* s = reinterpret_cast<const uint4*>(Wp);
        uint4* d = reinterpret_cast<uint4*>(sW);
        for (int i = threadIdx.x; i < WMAT / 4; i += ROW_WARPS * 32) d[i] = s[i];
        if (threadIdx.x < H) sBias[threadIdx.x] = bias ? bias[threadIdx.x] : 0.f;
    }
    __syncthreads();

    int lane = threadIdx.x & 31;
    int warp = threadIdx.x >> 5;
    int r = lane >> 2, t = lane & 3;
    unsigned* bufHi = bufAll + warp * SWARP;
    unsigned* bufLo = bufHi + 1088;

    int nTiles = (n + 15) >> 4;
    for (int tile = blockIdx.x * ROW_WARPS + warp; tile < nTiles;
         tile += gridDim.x * ROW_WARPS) {
        int row0 = tile * 16;
#pragma unroll
        for (int e = 0; e < 16; ++e) {
            int rw = row0 + e;
            float4 x = (rw < n) ? reinterpret_cast<const float4*>(X)[rw * H4 + lane]
                                : make_float4(0.f, 0.f, 0.f, 0.f);
            float h0,l0,h1,l1,h2,l2,h3,l3;
            bsplit(x.x,h0,l0); bsplit(x.y,h1,l1); bsplit(x.z,h2,l2); bsplit(x.w,h3,l3);
            *reinterpret_cast<uint2*>(bufHi + e * SROW + 2 * lane) = make_uint2(pbf2(h0,h1), pbf2(h2,h3));
            *reinterpret_cast<uint2*>(bufLo + e * SROW + 2 * lane) = make_uint2(pbf2(l0,l1), pbf2(l2,l3));
        }
        __syncwarp();
        unsigned ah[8][4], al[8][4];
        load_frags(bufHi, bufLo, r, t, ah, al);
        __syncwarp();

        int gr_lo = row0 + r, gr_hi = row0 + r + 8;
        bool ok_lo = gr_lo < n, ok_hi = gr_hi < n;

#pragma unroll 4
        for (int nb = 0; nb < 16; ++nb) {
            float acc[4] = {0.f, 0.f, 0.f, 0.f};
            gemm_nb(acc, ah, al, reinterpret_cast<const uint2*>(sW), nb, lane);

            int c0 = nb * 8 + 2 * t;
            float2 p = *reinterpret_cast<const float2*>(&sBias[c0]);
            float v0 = acc[0] + p.x, v1 = acc[1] + p.y;
            float v2 = acc[2] + p.x, v3 = acc[3] + p.y;
            if (R) {
                if (ok_lo) {
                    float2 r0 = *reinterpret_cast<const float2*>(&R[gr_lo * H + c0]);
                    v0 += r0.x; v1 += r0.y;
                }
                if (ok_hi) {
                    float2 r1 = *reinterpret_cast<const float2*>(&R[gr_hi * H + c0]);
                    v2 += r1.x; v3 += r1.y;
                }
            }
            if (SILU_) { v0 = silu(v0); v1 = silu(v1); v2 = silu(v2); v3 = silu(v3); }
            if (ok_lo) *reinterpret_cast<float2*>(&Y[gr_lo * H + c0]) = make_float2(v0, v1);
            if (ok_hi) *reinterpret_cast<float2*>(&Y[gr_hi * H + c0]) = make_float2(v2, v3);
        }
    }
}

// ---------------- dual-output row GEMM: Pu = X@Wu, Pv = X@Wv ----------------
// Stages/fragments X once, runs both weight images.
__global__ void __launch_bounds__(ROW2_WARPS * 32, 1)
k_rowgemm2(const float* __restrict__ X,
           const unsigned* __restrict__ WpU, const unsigned* __restrict__ WpV,
           float* __restrict__ YU, float* __restrict__ YV, int n)
{
    extern __shared__ float smem[];
    unsigned* sWu = reinterpret_cast<unsigned*>(smem);
    unsigned* sWv = sWu + WMAT;
    unsigned* bufAll = sWu + 2 * WMAT;

    {
        const uint4* su = reinterpret_cast<const uint4*>(WpU);
        const uint4* sv = reinterpret_cast<const uint4*>(WpV);
        uint4* du = reinterpret_cast<uint4*>(sWu);
        uint4* dv = reinterpret_cast<uint4*>(sWv);
        for (int i = threadIdx.x; i < WMAT / 4; i += ROW2_WARPS * 32) {
            du[i] = su[i]; dv[i] = sv[i];
        }
    }
    __syncthreads();

    int lane = threadIdx.x & 31;
    int warp = threadIdx.x >> 5;
    int r = lane >> 2, t = lane & 3;
    unsigned* bufHi = bufAll + warp * SWARP;
    unsigned* bufLo = bufHi + 1088;

    int nTiles = (n + 15) >> 4;
    for (int tile = blockIdx.x * ROW2_WARPS + warp; tile < nTiles;
         tile += gridDim.x * ROW2_WARPS) {
        int row0 = tile * 16;
#pragma unroll
        for (int e = 0; e < 16; ++e) {
            int rw = row0 + e;
            float4 x = (rw < n) ? reinterpret_cast<const float4*>(X)[rw * H4 + lane]
                                : make_float4(0.f, 0.f, 0.f, 0.f);
            float h0,l0,h1,l1,h2,l2,h3,l3;
            bsplit(x.x,h0,l0); bsplit(x.y,h1,l1); bsplit(x.z,h2,l2); bsplit(x.w,h3,l3);
            *reinterpret_cast<uint2*>(bufHi + e * SROW + 2 * lane) = make_uint2(pbf2(h0,h1), pbf2(h2,h3));
            *reinterpret_cast<uint2*>(bufLo + e * SROW + 2 * lane) = make_uint2(pbf2(l0,l1), pbf2(l2,l3));
        }
        __syncwarp();
        unsigned ah[8][4], al[8][4];
        load_frags(bufHi, bufLo, r, t, ah, al);
        __syncwarp();

        int gr_lo = row0 + r, gr_hi = row0 + r + 8;
        bool ok_lo = gr_lo < n, ok_hi = gr_hi < n;

#pragma unroll 2
        for (int nb = 0; nb < 16; ++nb) {
            int c0 = nb * 8 + 2 * t;
            float accU[4] = {0.f, 0.f, 0.f, 0.f};
            gemm_nb(accU, ah, al, reinterpret_cast<const uint2*>(sWu), nb, lane);
            if (ok_lo) *reinterpret_cast<float2*>(&YU[gr_lo * H + c0]) = make_float2(accU[0], accU[1]);
            if (ok_hi) *reinterpret_cast<float2*>(&YU[gr_hi * H + c0]) = make_float2(accU[2], accU[3]);

            float accV[4] = {0.f, 0.f, 0.f, 0.f};
            gemm_nb(accV, ah, al, reinterpret_cast<const uint2*>(sWv), nb, lane);
            if (ok_lo) *reinterpret_cast<float2*>(&YV[gr_lo * H + c0]) = make_float2(accV[0], accV[1]);
            if (ok_hi) *reinterpret_cast<float2*>(&YV[gr_hi * H + c0]) = make_float2(accV[2], accV[3]);
        }
    }
}

// ---------------- fused edge block (tensor core, bf16x3) ----------------
// GEMM1 output fragments ARE the GEMM2 input fragments (C-layout at
// nb=2kb,2kb+1 == A-layout at kb), so no smem restage between GEMMs.
// Staging gathers are software-pipelined (depth 4) to hide L2 latency.
__global__ void __launch_bounds__(EDGE_WARPS * 32, 1)
k_edge_mma(const float* __restrict__ Pu, const float* __restrict__ Pv,
           const float* __restrict__ dis,
           const int* __restrict__ idu, const int* __restrict__ idv,
           const float* __restrict__ wdis, const float* __restrict__ b1,
           const unsigned* __restrict__ W2p, const float* __restrict__ b2,
           const unsigned* __restrict__ W3p, const float* __restrict__ b3,
           float* __restrict__ aOut, int E)
{
    extern __shared__ float smem[];
    unsigned* sW2 = reinterpret_cast<unsigned*>(smem);          // WMAT
    unsigned* sW3 = reinterpret_cast<unsigned*>(smem) + WMAT;   // WMAT
    float* sB2 = smem + 2 * WMAT;
    float* sB3 = smem + 2 * WMAT + 128;
    unsigned* bufAll = reinterpret_cast<unsigned*>(smem + 2 * WMAT + 256);

    {
        const uint4* s2 = reinterpret_cast<const uint4*>(W2p);
        const uint4* s3 = reinterpret_cast<const uint4*>(W3p);
        uint4* d2 = reinterpret_cast<uint4*>(sW2);
        uint4* d3 = reinterpret_cast<uint4*>(sW3);
        for (int i = threadIdx.x; i < WMAT / 4; i += EDGE_WARPS * 32) { d2[i] = s2[i]; d3[i] = s3[i]; }
        if (threadIdx.x < H) { sB2[threadIdx.x] = b2[threadIdx.x]; sB3[threadIdx.x] = b3[threadIdx.x]; }
    }
    __syncthreads();

    int lane = threadIdx.x & 31;
    int warp = threadIdx.x >> 5;
    int r = lane >> 2, t = lane & 3;
    unsigned* bufHi = bufAll + warp * SWARP;
    unsigned* bufLo = bufHi + 1088;
    float* scat = reinterpret_cast<float*>(bufHi);   // fp32 16x132, reused after frag load

    float4 wd  = reinterpret_cast<const float4*>(wdis)[lane];
    float4 bb1 = reinterpret_cast<const float4*>(b1)[lane];

    const float4* Pu4 = reinterpret_cast<const float4*>(Pu);
    const float4* Pv4 = reinterpret_cast<const float4*>(Pv);

    int nTiles = (E + 15) >> 4;
    for (int tile = blockIdx.x * EDGE_WARPS + warp; tile < nTiles;
         tile += gridDim.x * EDGE_WARPS) {
        int e0 = tile * 16;
        int u_s = 0, v_s = 0; float d_s = 0.f;
        if (lane < 16 && e0 + lane < E) {
            u_s = idu[e0 + lane]; v_s = idv[e0 + lane]; d_s = dis[e0 + lane];
        }

        // ---- stage t1 = silu(Pu[u] + Pv[v] + d*Wdis + b1) as bf16 hi/lo ----
        // depth-4 prefetch ring to keep 8 gathers in flight.
        float4 fu[4], fv[4];
#pragma unroll
        for (int j = 0; j < 4; ++j) {
            int u = __shfl_sync(0xffffffffu, u_s, j);
            int v = __shfl_sync(0xffffffffu, v_s, j);
            fu[j] = Pu4[(size_t)u * H4 + lane];
            fv[j] = Pv4[(size_t)v * H4 + lane];
        }
#pragma unroll
        for (int e = 0; e < 16; ++e) {
            float4 pu = fu[e & 3];
            float4 pv = fv[e & 3];
            if (e < 12) {
                int u = __shfl_sync(0xffffffffu, u_s, e + 4);
                int v = __shfl_sync(0xffffffffu, v_s, e + 4);
                fu[e & 3] = Pu4[(size_t)u * H4 + lane];
                fv[e & 3] = Pv4[(size_t)v * H4 + lane];
            }
            float d = __shfl_sync(0xffffffffu, d_s, e);
            float t0 = silu(pu.x + pv.x + d * wd.x + bb1.x);
            float t1v = silu(pu.y + pv.y + d * wd.y + bb1.y);
            float t2v = silu(pu.z + pv.z + d * wd.z + bb1.z);
            float t3 = silu(pu.w + pv.w + d * wd.w + bb1.w);
            float h0,l0,h1,l1,h2,l2,h3,l3;
            bsplit(t0,h0,l0); bsplit(t1v,h1,l1); bsplit(t2v,h2,l2); bsplit(t3,h3,l3);
            *reinterpret_cast<uint2*>(bufHi + e * SROW + 2 * lane) = make_uint2(pbf2(h0,h1), pbf2(h2,h3));
            *reinterpret_cast<uint2*>(bufLo + e * SROW + 2 * lane) = make_uint2(pbf2(l0,l1), pbf2(l2,l3));
        }
        __syncwarp();
        unsigned ah[8][4], al[8][4];
        load_frags(bufHi, bufLo, r, t, ah, al);
        __syncwarp();

        // ---- GEMM1: t2 = silu(t1 @ W2 + b2), outputs become GEMM2 A-frags ----
        unsigned bh[8][4], bl[8][4];
#pragma unroll
        for (int kb = 0; kb < 8; ++kb) {
#pragma unroll
            for (int s = 0; s < 2; ++s) {
                int nb = 2 * kb + s;
                float acc[4] = {0.f, 0.f, 0.f, 0.f};
                gemm_nb(acc, ah, al, reinterpret_cast<const uint2*>(sW2), nb, lane);
                int c0 = nb * 8 + 2 * t;
                float2 p = *reinterpret_cast<const float2*>(&sB2[c0]);
                float v0 = silu(acc[0] + p.x), v1 = silu(acc[1] + p.y);
                float v2 = silu(acc[2] + p.x), v3 = silu(acc[3] + p.y);
                float h0,l0,h1,l1,h2,l2,h3,l3;
                bsplit(v0,h0,l0); bsplit(v1,h1,l1);
                bsplit(v2,h2,l2); bsplit(v3,h3,l3);
                bh[kb][2*s]     = pbf2(h0, h1);  bl[kb][2*s]     = pbf2(l0, l1);
                bh[kb][2*s + 1] = pbf2(h2, h3);  bl[kb][2*s + 1] = pbf2(l2, l3);
            }
        }

        // ---- GEMM2: m = t2 @ W3 + b3 -> stage fp32, then red.v4 scatter ----
#pragma unroll 4
        for (int nb = 0; nb < 16; ++nb) {
            float acc[4] = {0.f, 0.f, 0.f, 0.f};
            gemm_nb(acc, bh, bl, reinterpret_cast<const uint2*>(sW3), nb, lane);
            int c0 = nb * 8 + 2 * t;
            float2 q = *reinterpret_cast<const float2*>(&sB3[c0]);
            *reinterpret_cast<float2*>(&scat[r * 132 + c0])       = make_float2(acc[0] + q.x, acc[1] + q.y);
            *reinterpret_cast<float2*>(&scat[(r + 8) * 132 + c0]) = make_float2(acc[2] + q.x, acc[3] + q.y);
        }
        __syncwarp();

#pragma unroll 4
        for (int e = 0; e < 16; ++e) {
            if (e0 + e >= E) break;
            int u = __shfl_sync(0xffffffffu, u_s, e);
            int v = __shfl_sync(0xffffffffu, v_s, e);
            float4 mv = *reinterpret_cast<const float4*>(&scat[e * 132 + 4 * lane]);
            redv4(aOut + (size_t)u * H + 4 * lane, mv);
            redv4(aOut + (size_t)v * H + 4 * lane, mv);
        }
        __syncwarp();
    }
}

// ---------------- host launch ----------------
extern "C" void kernel_launch(void* const* d_in, const int* in_sizes, int n_in,
                              void* d_out, int out_size)
{
    const int*   atom = (const int*)  d_in[0];
    const float* dis1 = (const float*)d_in[1];
    const float* dis2 = (const float*)d_in[2];
    const int*   id1u = (const int*)  d_in[3];
    const int*   id1v = (const int*)  d_in[4];
    const int*   id2u = (const int*)  d_in[5];
    const int*   id2v = (const int*)  d_in[6];
    const float* emb  = (const float*)d_in[7];
    const float* Wu   = (const float*)d_in[8];
    const float* Wv   = (const float*)d_in[9];
    const float* Wdis = (const float*)d_in[10];
    const float* eb1  = (const float*)d_in[11];
    const float* eW2  = (const float*)d_in[12];
    const float* eb2  = (const float*)d_in[13];
    const float* eW3  = (const float*)d_in[14];
    const float* eb3  = (const float*)d_in[15];
    const float* Wh   = (const float*)d_in[16];
    const float* Wa1  = (const float*)d_in[17];
    const float* Wa2  = (const float*)d_in[18];
    const float* ub1  = (const float*)d_in[19];
    const float* uW2  = (const float*)d_in[20];
    const float* ub2  = (const float*)d_in[21];
    const float* outW = (const float*)d_in[22];
    const float* outb = (const float*)d_in[23];

    int n = in_sizes[0];
    int E = in_sizes[3];
    if (n > NMAX) return;

    float *h, *Pu, *Pv, *a1, *a2, *g;
    unsigned* pk;
    cudaGetSymbolAddress((void**)&h,  g_h);
    cudaGetSymbolAddress((void**)&Pu, g_Pu);
    cudaGetSymbolAddress((void**)&Pv, g_Pv);
    cudaGetSymbolAddress((void**)&a1, g_a1);
    cudaGetSymbolAddress((void**)&a2, g_a2);
    cudaGetSymbolAddress((void**)&g,  g_g);
    cudaGetSymbolAddress((void**)&pk, g_pack);

    const int SM_ROW  = (WMAT + 128) * 4 + ROW_WARPS * SWARP * 4;      // 205312 B
    const int SM_ROW2 = 2 * WMAT * 4 + ROW2_WARPS * SWARP * 4;         // 218112 B
    const int SM_EDGE = (2 * WMAT + 256) * 4 + EDGE_WARPS * SWARP * 4; // 219136 B

    cudaFuncSetAttribute(k_rowgemm_mma<false>,
                         cudaFuncAttributeMaxDynamicSharedMemorySize, SM_ROW);
    cudaFuncSetAttribute(k_rowgemm_mma<true>,
                         cudaFuncAttributeMaxDynamicSharedMemorySize, SM_ROW);
    cudaFuncSetAttribute(k_rowgemm2,
                         cudaFuncAttributeMaxDynamicSharedMemorySize, SM_ROW2);
    cudaFuncSetAttribute(k_edge_mma,
                         cudaFuncAttributeMaxDynamicSharedMemorySize, SM_EDGE);

    int gthreads = n * H4;
    int gblocks  = (gthreads + 255) / 256;

    k_pack<<<dim3(2, 24), 256>>>(Wu, Wv, eW2, eW3, Wh, Wa1, Wa2, uW2);
    k_gather<<<gblocks, 256>>>(atom, emb, h, n);

    for (int L = 0; L < 2; ++L) {
        k_zero2<<<gblocks, 256>>>(a1, a2, n * H4);

        int i1 = 2 * L, i2 = 2 * L + 1;

        // edge block i1 (graph 1) -> a1
        k_rowgemm2<<<148, ROW2_WARPS * 32, SM_ROW2>>>(
            h, pk + (0 + i1) * WMAT, pk + (4 + i1) * WMAT, Pu, Pv, n);
        k_edge_mma<<<148, EDGE_WARPS * 32, SM_EDGE>>>(
            Pu, Pv, dis1, id1u, id1v,
            Wdis + i1 * H, eb1 + i1 * H,
            pk + (8 + i1) * WMAT, eb2 + i1 * H,
            pk + (12 + i1) * WMAT, eb3 + i1 * H, a1, E);

        // edge block i2 (graph 2) -> a2
        k_rowgemm2<<<148, ROW2_WARPS * 32, SM_ROW2>>>(
            h, pk + (0 + i2) * WMAT, pk + (4 + i2) * WMAT, Pu, Pv, n);
        k_edge_mma<<<148, EDGE_WARPS * 32, SM_EDGE>>>(
            Pu, Pv, dis2, id2u, id2v,
            Wdis + i2 * H, eb1 + i2 * H,
            pk + (8 + i2) * WMAT, eb2 + i2 * H,
            pk + (12 + i2) * WMAT, eb3 + i2 * H, a2, E);

        // atom update L:
        //   g = h @ Wh ; g += a1 @ Wa1 ; g = silu(g + a2 @ Wa2 + ub1)
        //   h = g @ uW2 + ub2 + h
        k_rowgemm_mma<false><<<148, ROW_WARPS * 32, SM_ROW>>>(h,  pk + (16 + L) * WMAT, 0,           0, g, n);
        k_rowgemm_mma<false><<<148, ROW_WARPS * 32, SM_ROW>>>(a1, pk + (18 + L) * WMAT, 0,           g, g, n);
        k_rowgemm_mma<true ><<<148, ROW_WARPS * 32, SM_ROW>>>(a2, pk + (20 + L) * WMAT, ub1 + L * H, g, g, n);
        k_rowgemm_mma<false><<<148, ROW_WARPS * 32, SM_ROW>>>(g,  pk + (22 + L) * WMAT, ub2 + L * H, h, h, n);
    }

    k_out<<<gblocks, 256>>>(h, outW, outb, (float*)d_out, n);
}

// round 11
// speedup vs baseline: 4.7682x; 1.1244x over previous
#include <cuda_runtime.h>
#include <cuda_bf16.h>
#include <stdint.h>
#include <math.h>

#define H 128
#define H4 32
#define NMAX 50176
#define WMAT 16384   // packed weight footprint in unsigneds per matrix (hi+lo)

// ---------------- device scratch (static, no allocation) ----------------
__device__ float g_h [NMAX * H];
__device__ float g_Pu[NMAX * H];
__device__ float g_Pv[NMAX * H];
__device__ float g_a1[NMAX * H];
__device__ float g_a2[NMAX * H];
__device__ float g_g [NMAX * H];
__device__ unsigned g_pack[24 * WMAT];   // bf16 hi/lo fragment-packed weights

// ---------------- helpers ----------------
__device__ __forceinline__ float silu(float x) { return x / (1.0f + __expf(-x)); }

__device__ __forceinline__ unsigned pbf2(float a, float b) {
    unsigned r;
    asm("cvt.rn.bf16x2.f32 %0, %1, %2;" : "=r"(r) : "f"(b), "f"(a));
    return r;
}

__device__ __forceinline__ void bsplit(float x, float& hi, float& lo) {
    __nv_bfloat16 h = __float2bfloat16(x);
    hi = __bfloat162float(h);
    lo = x - hi;
}

// m16n8k16 bf16 mma, D += A*B
__device__ __forceinline__ void mma16(float* c, const unsigned* a, uint2 b) {
    asm volatile(
        "mma.sync.aligned.m16n8k16.row.col.f32.bf16.bf16.f32 "
        "{%0,%1,%2,%3},{%4,%5,%6,%7},{%8,%9},{%0,%1,%2,%3};"
        : "+f"(c[0]), "+f"(c[1]), "+f"(c[2]), "+f"(c[3])
        : "r"(a[0]), "r"(a[1]), "r"(a[2]), "r"(a[3]), "r"(b.x), "r"(b.y));
}

// vectorized reduction atomic: p[0..3] += v
__device__ __forceinline__ void redv4(float* p, float4 v) {
    asm volatile("red.global.add.v4.f32 [%0], {%1,%2,%3,%4};"
                 :: "l"(p), "f"(v.x), "f"(v.y), "f"(v.z), "f"(v.w) : "memory");
}

// ---------------- weight packing ----------------
__global__ void k_pack(const float* __restrict__ Wu,  const float* __restrict__ Wv,
                       const float* __restrict__ eW2, const float* __restrict__ eW3,
                       const float* __restrict__ Wh,  const float* __restrict__ Wa1,
                       const float* __restrict__ Wa2, const float* __restrict__ uW2)
{
    int m = blockIdx.y;
    const float* src;
    if      (m < 4)  src = Wu  + m * H * H;
    else if (m < 8)  src = Wv  + (m - 4) * H * H;
    else if (m < 12) src = eW2 + (m - 8) * H * H;
    else if (m < 16) src = eW3 + (m - 12) * H * H;
    else if (m < 18) src = Wh  + (m - 16) * H * H;
    else if (m < 20) src = Wa1 + (m - 18) * H * H;
    else if (m < 22) src = Wa2 + (m - 20) * H * H;
    else             src = uW2 + (m - 22) * H * H;

    uint2* dhi = reinterpret_cast<uint2*>(g_pack + m * WMAT);
    uint2* dlo = dhi + 4096;

    for (int idx = blockIdx.x * blockDim.x + threadIdx.x; idx < 4096;
         idx += gridDim.x * blockDim.x) {
        int lane = idx & 31, kbnb = idx >> 5;
        int t = lane & 3, g = lane >> 2;
        int kb = kbnb & 7, nb = kbnb >> 3;
        int k0 = kb * 16 + 2 * t;
        int n  = nb * 8 + g;
        float w0 = src[(k0    ) * H + n];
        float w1 = src[(k0 + 1) * H + n];
        float w8 = src[(k0 + 8) * H + n];
        float w9 = src[(k0 + 9) * H + n];
        float h0, l0, h1, l1, h8, l8, h9, l9;
        bsplit(w0, h0, l0); bsplit(w1, h1, l1);
        bsplit(w8, h8, l8); bsplit(w9, h9, l9);
        dhi[idx] = make_uint2(pbf2(h0, h1), pbf2(h8, h9));
        dlo[idx] = make_uint2(pbf2(l0, l1), pbf2(l8, l9));
    }
}

// ---------------- misc kernels ----------------
__global__ void k_gather(const int* __restrict__ atom,
                         const float* __restrict__ emb,
                         float* __restrict__ h, int n)
{
    int i = blockIdx.x * blockDim.x + threadIdx.x;
    if (i >= n * H4) return;
    int row = i >> 5, col = i & 31;
    reinterpret_cast<float4*>(h)[i] =
        reinterpret_cast<const float4*>(emb)[atom[row] * H4 + col];
}

__global__ void k_zero2(float* __restrict__ a, float* __restrict__ b, int n4)
{
    int i = blockIdx.x * blockDim.x + threadIdx.x;
    if (i >= n4) return;
    float4 z = make_float4(0.f, 0.f, 0.f, 0.f);
    reinterpret_cast<float4*>(a)[i] = z;
    reinterpret_cast<float4*>(b)[i] = z;
}

__global__ void k_out(const float* __restrict__ h,
                      const float* __restrict__ outW,
                      const float* __restrict__ outb,
                      float* __restrict__ out, int n)
{
    int warp = (blockIdx.x * blockDim.x + threadIdx.x) >> 5;
    int lane = threadIdx.x & 31;
    if (warp >= n) return;
    float4 x = reinterpret_cast<const float4*>(h)[warp * H4 + lane];
    int k0 = lane * 4;
    float s0 = x.x * outW[(k0+0)*3+0] + x.y * outW[(k0+1)*3+0]
             + x.z * outW[(k0+2)*3+0] + x.w * outW[(k0+3)*3+0];
    float s1 = x.x * outW[(k0+0)*3+1] + x.y * outW[(k0+1)*3+1]
             + x.z * outW[(k0+2)*3+1] + x.w * outW[(k0+3)*3+1];
    float s2 = x.x * outW[(k0+0)*3+2] + x.y * outW[(k0+1)*3+2]
             + x.z * outW[(k0+2)*3+2] + x.w * outW[(k0+3)*3+2];
#pragma unroll
    for (int off = 16; off; off >>= 1) {
        s0 += __shfl_xor_sync(0xffffffffu, s0, off);
        s1 += __shfl_xor_sync(0xffffffffu, s1, off);
        s2 += __shfl_xor_sync(0xffffffffu, s2, off);
    }
    if (lane == 0) {
        out[warp*3+0] = s0 + outb[0];
        out[warp*3+1] = s1 + outb[1];
        out[warp*3+2] = s2 + outb[2];
    }
}

// ---------------- staging constants ----------------
#define SROW 68
#define SWARP 2176
#define EDGE_WARPS 11
#define ROW_WARPS 16
#define ROW2_WARPS 11

// load A fragments (hi+lo) for all 8 kb blocks from staging buffers
__device__ __forceinline__ void load_frags(const unsigned* bufHi, const unsigned* bufLo,
                                           int r, int t,
                                           unsigned ah[8][4], unsigned al[8][4])
{
#pragma unroll
    for (int kb = 0; kb < 8; ++kb) {
        int o0 = r * SROW + kb * 8 + t;
        int o1 = (r + 8) * SROW + kb * 8 + t;
        ah[kb][0] = bufHi[o0];     ah[kb][1] = bufHi[o1];
        ah[kb][2] = bufHi[o0 + 4]; ah[kb][3] = bufHi[o1 + 4];
        al[kb][0] = bufLo[o0];     al[kb][1] = bufLo[o1];
        al[kb][2] = bufLo[o0 + 4]; al[kb][3] = bufLo[o1 + 4];
    }
}

// bf16x3 split GEMM over TWO nb column blocks with FOUR independent
// accumulator chains (2 nb x 2 kb-parity), depth 12 each.
__device__ __forceinline__ void gemm_nb_pair(float acc0[4], float acc1[4],
                                             const unsigned ah[8][4],
                                             const unsigned al[8][4],
                                             const uint2* sW, int nb0, int lane)
{
    const uint2* B0h = sW + nb0 * 256 + lane;
    const uint2* B0l = B0h + 4096;
    const uint2* B1h = B0h + 256;
    const uint2* B1l = B0l + 256;
    float e0[4] = {0.f,0.f,0.f,0.f};
    float e1[4] = {0.f,0.f,0.f,0.f};
#pragma unroll
    for (int kb = 0; kb < 8; kb += 2) {
        uint2 b0h = B0h[kb * 32],      b0l = B0l[kb * 32];
        uint2 b1h = B1h[kb * 32],      b1l = B1l[kb * 32];
        uint2 c0h = B0h[(kb+1) * 32],  c0l = B0l[(kb+1) * 32];
        uint2 c1h = B1h[(kb+1) * 32],  c1l = B1l[(kb+1) * 32];
        mma16(acc0, ah[kb],   b0h);  mma16(acc1, ah[kb],   b1h);
        mma16(e0,   ah[kb+1], c0h);  mma16(e1,   ah[kb+1], c1h);
        mma16(acc0, al[kb],   b0h);  mma16(acc1, al[kb],   b1h);
        mma16(e0,   al[kb+1], c0h);  mma16(e1,   al[kb+1], c1h);
        mma16(acc0, ah[kb],   b0l);  mma16(acc1, ah[kb],   b1l);
        mma16(e0,   ah[kb+1], c0l);  mma16(e1,   ah[kb+1], c1l);
    }
#pragma unroll
    for (int i = 0; i < 4; ++i) { acc0[i] += e0[i]; acc1[i] += e1[i]; }
}

// ---------------- tensor-core row GEMM ----------------
// Y = [silu]( X @ W + bias? + R? )
template<bool SILU_>
__global__ void __launch_bounds__(ROW_WARPS * 32, 1)
k_rowgemm_mma(const float* __restrict__ X, const unsigned* __restrict__ Wp,
              const float* __restrict__ bias, const float* __restrict__ R,
              float* __restrict__ Y, int n)
{
    extern __shared__ float smem[];
    unsigned* sW    = reinterpret_cast<unsigned*>(smem);
    float*    sBias = smem + WMAT;
    unsigned* bufAll = reinterpret_cast<unsigned*>(smem + WMAT + 128);

    {
        const uint4* s = reinterpret_cast<const uint4*>(Wp);
        uint4* d = reinterpret_cast<uint4*>(sW);
        for (int i = threadIdx.x; i < WMAT / 4; i += ROW_WARPS * 32) d[i] = s[i];
        if (threadIdx.x < H) sBias[threadIdx.x] = bias ? bias[threadIdx.x] : 0.f;
    }
    __syncthreads();

    int lane = threadIdx.x & 31;
    int warp = threadIdx.x >> 5;
    int r = lane >> 2, t = lane & 3;
    unsigned* bufHi = bufAll + warp * SWARP;
    unsigned* bufLo = bufHi + 1088;

    int nTiles = (n + 15) >> 4;
    for (int tile = blockIdx.x * ROW_WARPS + warp; tile < nTiles;
         tile += gridDim.x * ROW_WARPS) {
        int row0 = tile * 16;
#pragma unroll
        for (int e = 0; e < 16; ++e) {
            int rw = row0 + e;
            float4 x = (rw < n) ? reinterpret_cast<const float4*>(X)[rw * H4 + lane]
                                : make_float4(0.f, 0.f, 0.f, 0.f);
            float h0,l0,h1,l1,h2,l2,h3,l3;
            bsplit(x.x,h0,l0); bsplit(x.y,h1,l1); bsplit(x.z,h2,l2); bsplit(x.w,h3,l3);
            *reinterpret_cast<uint2*>(bufHi + e * SROW + 2 * lane) = make_uint2(pbf2(h0,h1), pbf2(h2,h3));
            *reinterpret_cast<uint2*>(bufLo + e * SROW + 2 * lane) = make_uint2(pbf2(l0,l1), pbf2(l2,l3));
        }
        __syncwarp();
        unsigned ah[8][4], al[8][4];
        load_frags(bufHi, bufLo, r, t, ah, al);
        __syncwarp();

        int gr_lo = row0 + r, gr_hi = row0 + r + 8;
        bool ok_lo = gr_lo < n, ok_hi = gr_hi < n;

#pragma unroll 2
        for (int nb = 0; nb < 16; nb += 2) {
            float acc0[4] = {0.f,0.f,0.f,0.f};
            float acc1[4] = {0.f,0.f,0.f,0.f};
            gemm_nb_pair(acc0, acc1, ah, al, reinterpret_cast<const uint2*>(sW), nb, lane);

#pragma unroll
            for (int s = 0; s < 2; ++s) {
                float* acc = s ? acc1 : acc0;
                int c0 = (nb + s) * 8 + 2 * t;
                float2 p = *reinterpret_cast<const float2*>(&sBias[c0]);
                float v0 = acc[0] + p.x, v1 = acc[1] + p.y;
                float v2 = acc[2] + p.x, v3 = acc[3] + p.y;
                if (R) {
                    if (ok_lo) {
                        float2 r0 = *reinterpret_cast<const float2*>(&R[gr_lo * H + c0]);
                        v0 += r0.x; v1 += r0.y;
                    }
                    if (ok_hi) {
                        float2 r1 = *reinterpret_cast<const float2*>(&R[gr_hi * H + c0]);
                        v2 += r1.x; v3 += r1.y;
                    }
                }
                if (SILU_) { v0 = silu(v0); v1 = silu(v1); v2 = silu(v2); v3 = silu(v3); }
                if (ok_lo) *reinterpret_cast<float2*>(&Y[gr_lo * H + c0]) = make_float2(v0, v1);
                if (ok_hi) *reinterpret_cast<float2*>(&Y[gr_hi * H + c0]) = make_float2(v2, v3);
            }
        }
    }
}

// ---------------- dual-output row GEMM: Pu = X@Wu, Pv = X@Wv ----------------
__global__ void __launch_bounds__(ROW2_WARPS * 32, 1)
k_rowgemm2(const float* __restrict__ X,
           const unsigned* __restrict__ WpU, const unsigned* __restrict__ WpV,
           float* __restrict__ YU, float* __restrict__ YV, int n)
{
    extern __shared__ float smem[];
    unsigned* sWu = reinterpret_cast<unsigned*>(smem);
    unsigned* sWv = sWu + WMAT;
    unsigned* bufAll = sWu + 2 * WMAT;

    {
        const uint4* su = reinterpret_cast<const uint4*>(WpU);
        const uint4* sv = reinterpret_cast<const uint4*>(WpV);
        uint4* du = reinterpret_cast<uint4*>(sWu);
        uint4* dv = reinterpret_cast<uint4*>(sWv);
        for (int i = threadIdx.x; i < WMAT / 4; i += ROW2_WARPS * 32) {
            du[i] = su[i]; dv[i] = sv[i];
        }
    }
    __syncthreads();

    int lane = threadIdx.x & 31;
    int warp = threadIdx.x >> 5;
    int r = lane >> 2, t = lane & 3;
    unsigned* bufHi = bufAll + warp * SWARP;
    unsigned* bufLo = bufHi + 1088;

    int nTiles = (n + 15) >> 4;
    for (int tile = blockIdx.x * ROW2_WARPS + warp; tile < nTiles;
         tile += gridDim.x * ROW2_WARPS) {
        int row0 = tile * 16;
#pragma unroll
        for (int e = 0; e < 16; ++e) {
            int rw = row0 + e;
            float4 x = (rw < n) ? reinterpret_cast<const float4*>(X)[rw * H4 + lane]
                                : make_float4(0.f, 0.f, 0.f, 0.f);
            float h0,l0,h1,l1,h2,l2,h3,l3;
            bsplit(x.x,h0,l0); bsplit(x.y,h1,l1); bsplit(x.z,h2,l2); bsplit(x.w,h3,l3);
            *reinterpret_cast<uint2*>(bufHi + e * SROW + 2 * lane) = make_uint2(pbf2(h0,h1), pbf2(h2,h3));
            *reinterpret_cast<uint2*>(bufLo + e * SROW + 2 * lane) = make_uint2(pbf2(l0,l1), pbf2(l2,l3));
        }
        __syncwarp();
        unsigned ah[8][4], al[8][4];
        load_frags(bufHi, bufLo, r, t, ah, al);
        __syncwarp();

        int gr_lo = row0 + r, gr_hi = row0 + r + 8;
        bool ok_lo = gr_lo < n, ok_hi = gr_hi < n;

#pragma unroll 2
        for (int nb = 0; nb < 16; nb += 2) {
            float accU0[4] = {0.f,0.f,0.f,0.f};
            float accU1[4] = {0.f,0.f,0.f,0.f};
            gemm_nb_pair(accU0, accU1, ah, al, reinterpret_cast<const uint2*>(sWu), nb, lane);
            int c0 = nb * 8 + 2 * t, c1 = c0 + 8;
            if (ok_lo) {
                *reinterpret_cast<float2*>(&YU[gr_lo * H + c0]) = make_float2(accU0[0], accU0[1]);
                *reinterpret_cast<float2*>(&YU[gr_lo * H + c1]) = make_float2(accU1[0], accU1[1]);
            }
            if (ok_hi) {
                *reinterpret_cast<float2*>(&YU[gr_hi * H + c0]) = make_float2(accU0[2], accU0[3]);
                *reinterpret_cast<float2*>(&YU[gr_hi * H + c1]) = make_float2(accU1[2], accU1[3]);
            }

            float accV0[4] = {0.f,0.f,0.f,0.f};
            float accV1[4] = {0.f,0.f,0.f,0.f};
            gemm_nb_pair(accV0, accV1, ah, al, reinterpret_cast<const uint2*>(sWv), nb, lane);
            if (ok_lo) {
                *reinterpret_cast<float2*>(&YV[gr_lo * H + c0]) = make_float2(accV0[0], accV0[1]);
                *reinterpret_cast<float2*>(&YV[gr_lo * H + c1]) = make_float2(accV1[0], accV1[1]);
            }
            if (ok_hi) {
                *reinterpret_cast<float2*>(&YV[gr_hi * H + c0]) = make_float2(accV0[2], accV0[3]);
                *reinterpret_cast<float2*>(&YV[gr_hi * H + c1]) = make_float2(accV1[2], accV1[3]);
            }
        }
    }
}

// ---------------- fused edge block (tensor core, bf16x3) ----------------
__global__ void __launch_bounds__(EDGE_WARPS * 32, 1)
k_edge_mma(const float* __restrict__ Pu, const float* __restrict__ Pv,
           const float* __restrict__ dis,
           const int* __restrict__ idu, const int* __restrict__ idv,
           const float* __restrict__ wdis, const float* __restrict__ b1,
           const unsigned* __restrict__ W2p, const float* __restrict__ b2,
           const unsigned* __restrict__ W3p, const float* __restrict__ b3,
           float* __restrict__ aOut, int E)
{
    extern __shared__ float smem[];
    unsigned* sW2 = reinterpret_cast<unsigned*>(smem);          // WMAT
    unsigned* sW3 = reinterpret_cast<unsigned*>(smem) + WMAT;   // WMAT
    float* sB2 = smem + 2 * WMAT;
    float* sB3 = smem + 2 * WMAT + 128;
    unsigned* bufAll = reinterpret_cast<unsigned*>(smem + 2 * WMAT + 256);

    {
        const uint4* s2 = reinterpret_cast<const uint4*>(W2p);
        const uint4* s3 = reinterpret_cast<const uint4*>(W3p);
        uint4* d2 = reinterpret_cast<uint4*>(sW2);
        uint4* d3 = reinterpret_cast<uint4*>(sW3);
        for (int i = threadIdx.x; i < WMAT / 4; i += EDGE_WARPS * 32) { d2[i] = s2[i]; d3[i] = s3[i]; }
        if (threadIdx.x < H) { sB2[threadIdx.x] = b2[threadIdx.x]; sB3[threadIdx.x] = b3[threadIdx.x]; }
    }
    __syncthreads();

    int lane = threadIdx.x & 31;
    int warp = threadIdx.x >> 5;
    int r = lane >> 2, t = lane & 3;
    unsigned* bufHi = bufAll + warp * SWARP;
    unsigned* bufLo = bufHi + 1088;
    float* scat = reinterpret_cast<float*>(bufHi);   // fp32 16x132, reused after frag load

    float4 wd  = reinterpret_cast<const float4*>(wdis)[lane];
    float4 bb1 = reinterpret_cast<const float4*>(b1)[lane];

    const float4* Pu4 = reinterpret_cast<const float4*>(Pu);
    const float4* Pv4 = reinterpret_cast<const float4*>(Pv);

    int nTiles = (E + 15) >> 4;
    for (int tile = blockIdx.x * EDGE_WARPS + warp; tile < nTiles;
         tile += gridDim.x * EDGE_WARPS) {
        int e0 = tile * 16;
        int u_s = 0, v_s = 0; float d_s = 0.f;
        if (lane < 16 && e0 + lane < E) {
            u_s = idu[e0 + lane]; v_s = idv[e0 + lane]; d_s = dis[e0 + lane];
        }

        // ---- stage t1 = silu(Pu[u] + Pv[v] + d*Wdis + b1) as bf16 hi/lo ----
        float4 fu[4], fv[4];
#pragma unroll
        for (int j = 0; j < 4; ++j) {
            int u = __shfl_sync(0xffffffffu, u_s, j);
            int v = __shfl_sync(0xffffffffu, v_s, j);
            fu[j] = Pu4[(size_t)u * H4 + lane];
            fv[j] = Pv4[(size_t)v * H4 + lane];
        }
#pragma unroll
        for (int e = 0; e < 16; ++e) {
            float4 pu = fu[e & 3];
            float4 pv = fv[e & 3];
            if (e < 12) {
                int u = __shfl_sync(0xffffffffu, u_s, e + 4);
                int v = __shfl_sync(0xffffffffu, v_s, e + 4);
                fu[e & 3] = Pu4[(size_t)u * H4 + lane];
                fv[e & 3] = Pv4[(size_t)v * H4 + lane];
            }
            float d = __shfl_sync(0xffffffffu, d_s, e);
            float t0 = silu(pu.x + pv.x + d * wd.x + bb1.x);
            float t1v = silu(pu.y + pv.y + d * wd.y + bb1.y);
            float t2v = silu(pu.z + pv.z + d * wd.z + bb1.z);
            float t3 = silu(pu.w + pv.w + d * wd.w + bb1.w);
            float h0,l0,h1,l1,h2,l2,h3,l3;
            bsplit(t0,h0,l0); bsplit(t1v,h1,l1); bsplit(t2v,h2,l2); bsplit(t3,h3,l3);
            *reinterpret_cast<uint2*>(bufHi + e * SROW + 2 * lane) = make_uint2(pbf2(h0,h1), pbf2(h2,h3));
            *reinterpret_cast<uint2*>(bufLo + e * SROW + 2 * lane) = make_uint2(pbf2(l0,l1), pbf2(l2,l3));
        }
        __syncwarp();
        unsigned ah[8][4], al[8][4];
        load_frags(bufHi, bufLo, r, t, ah, al);
        __syncwarp();

        // ---- GEMM1: t2 = silu(t1 @ W2 + b2), outputs become GEMM2 A-frags ----
        unsigned bh[8][4], bl[8][4];
#pragma unroll
        for (int kb = 0; kb < 8; ++kb) {
            float acc0[4] = {0.f,0.f,0.f,0.f};
            float acc1[4] = {0.f,0.f,0.f,0.f};
            gemm_nb_pair(acc0, acc1, ah, al, reinterpret_cast<const uint2*>(sW2),
                         2 * kb, lane);
#pragma unroll
            for (int s = 0; s < 2; ++s) {
                float* acc = s ? acc1 : acc0;
                int c0 = (2 * kb + s) * 8 + 2 * t;
                float2 p = *reinterpret_cast<const float2*>(&sB2[c0]);
                float v0 = silu(acc[0] + p.x), v1 = silu(acc[1] + p.y);
                float v2 = silu(acc[2] + p.x), v3 = silu(acc[3] + p.y);
                float h0,l0,h1,l1,h2,l2,h3,l3;
                bsplit(v0,h0,l0); bsplit(v1,h1,l1);
                bsplit(v2,h2,l2); bsplit(v3,h3,l3);
                bh[kb][2*s]     = pbf2(h0, h1);  bl[kb][2*s]     = pbf2(l0, l1);
                bh[kb][2*s + 1] = pbf2(h2, h3);  bl[kb][2*s + 1] = pbf2(l2, l3);
            }
        }

        // ---- GEMM2: m = t2 @ W3 + b3 -> stage fp32, then red.v4 scatter ----
#pragma unroll 2
        for (int nb = 0; nb < 16; nb += 2) {
            float acc0[4] = {0.f,0.f,0.f,0.f};
            float acc1[4] = {0.f,0.f,0.f,0.f};
            gemm_nb_pair(acc0, acc1, bh, bl, reinterpret_cast<const uint2*>(sW3),
                         nb, lane);
#pragma unroll
            for (int s = 0; s < 2; ++s) {
                float* acc = s ? acc1 : acc0;
                int c0 = (nb + s) * 8 + 2 * t;
                float2 q = *reinterpret_cast<const float2*>(&sB3[c0]);
                *reinterpret_cast<float2*>(&scat[r * 132 + c0])       = make_float2(acc[0] + q.x, acc[1] + q.y);
                *reinterpret_cast<float2*>(&scat[(r + 8) * 132 + c0]) = make_float2(acc[2] + q.x, acc[3] + q.y);
            }
        }
        __syncwarp();

#pragma unroll 4
        for (int e = 0; e < 16; ++e) {
            if (e0 + e >= E) break;
            int u = __shfl_sync(0xffffffffu, u_s, e);
            int v = __shfl_sync(0xffffffffu, v_s, e);
            float4 mv = *reinterpret_cast<const float4*>(&scat[e * 132 + 4 * lane]);
            redv4(aOut + (size_t)u * H + 4 * lane, mv);
            redv4(aOut + (size_t)v * H + 4 * lane, mv);
        }
        __syncwarp();
    }
}

// ---------------- host launch ----------------
extern "C" void kernel_launch(void* const* d_in, const int* in_sizes, int n_in,
                              void* d_out, int out_size)
{
    const int*   atom = (const int*)  d_in[0];
    const float* dis1 = (const float*)d_in[1];
    const float* dis2 = (const float*)d_in[2];
    const int*   id1u = (const int*)  d_in[3];
    const int*   id1v = (const int*)  d_in[4];
    const int*   id2u = (const int*)  d_in[5];
    const int*   id2v = (const int*)  d_in[6];
    const float* emb  = (const float*)d_in[7];
    const float* Wu   = (const float*)d_in[8];
    const float* Wv   = (const float*)d_in[9];
    const float* Wdis = (const float*)d_in[10];
    const float* eb1  = (const float*)d_in[11];
    const float* eW2  = (const float*)d_in[12];
    const float* eb2  = (const float*)d_in[13];
    const float* eW3  = (const float*)d_in[14];
    const float* eb3  = (const float*)d_in[15];
    const float* Wh   = (const float*)d_in[16];
    const float* Wa1  = (const float*)d_in[17];
    const float* Wa2  = (const float*)d_in[18];
    const float* ub1  = (const float*)d_in[19];
    const float* uW2  = (const float*)d_in[20];
    const float* ub2  = (const float*)d_in[21];
    const float* outW = (const float*)d_in[22];
    const float* outb = (const float*)d_in[23];

    int n = in_sizes[0];
    int E = in_sizes[3];
    if (n > NMAX) return;

    float *h, *Pu, *Pv, *a1, *a2, *g;
    unsigned* pk;
    cudaGetSymbolAddress((void**)&h,  g_h);
    cudaGetSymbolAddress((void**)&Pu, g_Pu);
    cudaGetSymbolAddress((void**)&Pv, g_Pv);
    cudaGetSymbolAddress((void**)&a1, g_a1);
    cudaGetSymbolAddress((void**)&a2, g_a2);
    cudaGetSymbolAddress((void**)&g,  g_g);
    cudaGetSymbolAddress((void**)&pk, g_pack);

    const int SM_ROW  = (WMAT + 128) * 4 + ROW_WARPS * SWARP * 4;      // 205312 B
    const int SM_ROW2 = 2 * WMAT * 4 + ROW2_WARPS * SWARP * 4;         // 226816 B
    const int SM_EDGE = (2 * WMAT + 256) * 4 + EDGE_WARPS * SWARP * 4; // 227840 B

    cudaFuncSetAttribute(k_rowgemm_mma<false>,
                         cudaFuncAttributeMaxDynamicSharedMemorySize, SM_ROW);
    cudaFuncSetAttribute(k_rowgemm_mma<true>,
                         cudaFuncAttributeMaxDynamicSharedMemorySize, SM_ROW);
    cudaFuncSetAttribute(k_rowgemm2,
                         cudaFuncAttributeMaxDynamicSharedMemorySize, SM_ROW2);
    cudaFuncSetAttribute(k_edge_mma,
                         cudaFuncAttributeMaxDynamicSharedMemorySize, SM_EDGE);

    int gthreads = n * H4;
    int gblocks  = (gthreads + 255) / 256;

    k_pack<<<dim3(2, 24), 256>>>(Wu, Wv, eW2, eW3, Wh, Wa1, Wa2, uW2);
    k_gather<<<gblocks, 256>>>(atom, emb, h, n);

    for (int L = 0; L < 2; ++L) {
        k_zero2<<<gblocks, 256>>>(a1, a2, n * H4);

        int i1 = 2 * L, i2 = 2 * L + 1;

        // edge block i1 (graph 1) -> a1
        k_rowgemm2<<<148, ROW2_WARPS * 32, SM_ROW2>>>(
            h, pk + (0 + i1) * WMAT, pk + (4 + i1) * WMAT, Pu, Pv, n);
        k_edge_mma<<<148, EDGE_WARPS * 32, SM_EDGE>>>(
            Pu, Pv, dis1, id1u, id1v,
            Wdis + i1 * H, eb1 + i1 * H,
            pk + (8 + i1) * WMAT, eb2 + i1 * H,
            pk + (12 + i1) * WMAT, eb3 + i1 * H, a1, E);

        // edge block i2 (graph 2) -> a2
        k_rowgemm2<<<148, ROW2_WARPS * 32, SM_ROW2>>>(
            h, pk + (0 + i2) * WMAT, pk + (4 + i2) * WMAT, Pu, Pv, n);
        k_edge_mma<<<148, EDGE_WARPS * 32, SM_EDGE>>>(
            Pu, Pv, dis2, id2u, id2v,
            Wdis + i2 * H, eb1 + i2 * H,
            pk + (8 + i2) * WMAT, eb2 + i2 * H,
            pk + (12 + i2) * WMAT, eb3 + i2 * H, a2, E);

        // atom update L:
        //   g = h @ Wh ; g += a1 @ Wa1 ; g = silu(g + a2 @ Wa2 + ub1)
        //   h = g @ uW2 + ub2 + h
        k_rowgemm_mma<false><<<148, ROW_WARPS * 32, SM_ROW>>>(h,  pk + (16 + L) * WMAT, 0,           0, g, n);
        k_rowgemm_mma<false><<<148, ROW_WARPS * 32, SM_ROW>>>(a1, pk + (18 + L) * WMAT, 0,           g, g, n);
        k_rowgemm_mma<true ><<<148, ROW_WARPS * 32, SM_ROW>>>(a2, pk + (20 + L) * WMAT, ub1 + L * H, g, g, n);
        k_rowgemm_mma<false><<<148, ROW_WARPS * 32, SM_ROW>>>(g,  pk + (22 + L) * WMAT, ub2 + L * H, h, h, n);
    }

    k_out<<<gblocks, 256>>>(h, outW, outb, (float*)d_out, n);
}